// round 4
// baseline (speedup 1.0000x reference)
#include <cuda_runtime.h>

// Problem constants
#define BB 4
#define NT 1568
#define NH 16
#define HD 64
#define CC 1024
#define MROWS (BB * NT)          // 6272
#define QKVBLK (NT * HD)         // 100352 per (s,b,h)

// Scratch (device globals — no allocations allowed)
static __device__ __align__(16) float g_qkv[3 * BB * NH * NT * HD];  // [3][B][H][N][D]
static __device__ __align__(16) float g_obuf[MROWS * CC];            // [B*N][C]
static __device__ __align__(16) float g_ctab[NT * 60];
static __device__ __align__(16) float g_stab[NT * 60];

// ---------------------------------------------------------------------------
// RoPE table: angle(n, d) = pos_axis(n, d/20) * 10000^{-((d%20)%10)/10}
// ---------------------------------------------------------------------------
__global__ void rope_tab_k() {
    int i = blockIdx.x * 256 + threadIdx.x;
    if (i >= NT * 60) return;
    int n = i / 60;
    int d = i - n * 60;
    int axis = d / 20;
    int fi = (d % 20) % 10;
    int fr = n / 196;
    int inf = n - fr * 196;
    int hh = inf / 14;
    int ww = inf - hh * 14;
    float pos = (axis == 0) ? (float)fr : ((axis == 1) ? (float)hh : (float)ww);
    float omega = 1.0f / powf(10000.0f, (float)fi * 0.1f);
    float ang = pos * omega;
    g_ctab[i] = cosf(ang);
    g_stab[i] = sinf(ang);
}

// ---------------------------------------------------------------------------
// GEMM C = A * B^T  (A: [M,1024] K-major, B: [Nout,1024] K-major)
// 128x128 tile, BK=8, 256 threads, 8x8 microtile.
// EPI==0: QKV + fused RoPE, scatter to g_qkv.   M=6272, Nout=3072, A = x.
// EPI==1: proj + bias, write Cout.              M=6272, Nout=1024, A = g_obuf.
// ---------------------------------------------------------------------------
template <int EPI>
__global__ __launch_bounds__(256) void gemm_k(
    const float* __restrict__ A,
    const float* __restrict__ Bw,
    float* __restrict__ Cout,
    const float* __restrict__ bias)
{
    constexpr int K = 1024;
    __shared__ float As[8][132];
    __shared__ float Bs[8][132];

    const int tid = threadIdx.x;
    const int tx = tid & 15;
    const int ty = tid >> 4;
    const int bx = blockIdx.x;
    const int by = blockIdx.y;

    const float* Ap = (EPI == 1) ? g_obuf : A;
    const int ar = tid >> 1;
    const int ak = (tid & 1) * 4;
    const float* aptr = Ap + (by * 128 + ar) * K + ak;
    const float* bptr = Bw + (bx * 128 + ar) * K + ak;

    float acc[8][8];
#pragma unroll
    for (int r = 0; r < 8; r++)
#pragma unroll
        for (int c = 0; c < 8; c++) acc[r][c] = 0.0f;

    float4 av = *(const float4*)aptr;
    float4 bv = *(const float4*)bptr;

#pragma unroll 1
    for (int it = 0; it < K / 8; it++) {
        __syncthreads();
        As[ak + 0][ar] = av.x; As[ak + 1][ar] = av.y;
        As[ak + 2][ar] = av.z; As[ak + 3][ar] = av.w;
        Bs[ak + 0][ar] = bv.x; Bs[ak + 1][ar] = bv.y;
        Bs[ak + 2][ar] = bv.z; Bs[ak + 3][ar] = bv.w;
        __syncthreads();
        if (it + 1 < K / 8) {
            av = *(const float4*)(aptr + (it + 1) * 8);
            bv = *(const float4*)(bptr + (it + 1) * 8);
        }
#pragma unroll
        for (int k = 0; k < 8; k++) {
            float4 a0 = *(const float4*)&As[k][ty * 4];
            float4 a1 = *(const float4*)&As[k][64 + ty * 4];
            float4 b0 = *(const float4*)&Bs[k][tx * 4];
            float4 b1 = *(const float4*)&Bs[k][64 + tx * 4];
            float aa[8] = {a0.x, a0.y, a0.z, a0.w, a1.x, a1.y, a1.z, a1.w};
            float bb[8] = {b0.x, b0.y, b0.z, b0.w, b1.x, b1.y, b1.z, b1.w};
#pragma unroll
            for (int r = 0; r < 8; r++)
#pragma unroll
                for (int c = 0; c < 8; c++)
                    acc[r][c] = fmaf(aa[r], bb[c], acc[r][c]);
        }
    }

    if (EPI == 0) {
        // Fused RoPE + scatter to [3][B][H][N][D]. Rotation pairs (d even, d+1)
        // are adjacent columns -> partner is acc[r][c^1] within each 4-col group.
#pragma unroll
        for (int r = 0; r < 8; r++) {
            int m = by * 128 + ((r < 4) ? ty * 4 + r : 64 + ty * 4 + r - 4);
            int b = m / NT;
            int n = m - b * NT;
            int nb = n * 60;
#pragma unroll
            for (int c = 0; c < 8; c++) {
                int o = bx * 128 + ((c < 4) ? tx * 4 + c : 64 + tx * 4 + c - 4);
                int sidx = o >> 10;           // 0=q, 1=k, 2=v
                int rm = o & 1023;
                int hh = rm >> 6;
                int d = rm & 63;
                float v = acc[r][c];
                float ov = v;
                if (sidx < 2 && d < 60) {
                    float ct = g_ctab[nb + d];
                    float st = g_stab[nb + d];
                    float vp = acc[r][c ^ 1];
                    ov = (d & 1) ? fmaf(v, ct, vp * st) : fmaf(v, ct, -vp * st);
                }
                g_qkv[(((sidx * BB + b) * NH + hh) * NT + n) * HD + d] = ov;
            }
        }
    } else {
        float4 bb0 = *(const float4*)&bias[bx * 128 + tx * 4];
        float4 bb1 = *(const float4*)&bias[bx * 128 + 64 + tx * 4];
#pragma unroll
        for (int r = 0; r < 8; r++) {
            int m = by * 128 + ((r < 4) ? ty * 4 + r : 64 + ty * 4 + r - 4);
            float4 o0 = make_float4(acc[r][0] + bb0.x, acc[r][1] + bb0.y,
                                    acc[r][2] + bb0.z, acc[r][3] + bb0.w);
            float4 o1 = make_float4(acc[r][4] + bb1.x, acc[r][5] + bb1.y,
                                    acc[r][6] + bb1.z, acc[r][7] + bb1.w);
            *(float4*)&Cout[m * CC + bx * 128 + tx * 4] = o0;
            *(float4*)&Cout[m * CC + bx * 128 + 64 + tx * 4] = o1;
        }
    }
}

// ---------------------------------------------------------------------------
// Flash attention: grid (13 q-tiles, 64 bh). BQ=128, BK=64, 256 threads.
// Thread (ty,tx) owns S rows 8ty..+7, S cols 4tx..+3; O rows 8ty..+7, dims 4tx..+3.
// ---------------------------------------------------------------------------
#define ATTN_SMEM ((64 * 132 + 64 * 68 + 64 * 68 + 128 * 68) * 4)

__global__ __launch_bounds__(256, 2) void attn_k() {
    extern __shared__ float sm[];
    float* Qt = sm;                    // [64][132]  Qt[d][row]
    float* Kt = Qt + 64 * 132;         // [64][68]   Kt[d][key]
    float* Vs = Kt + 64 * 68;          // [64][68]   Vs[key][d]
    float* Ps = Vs + 64 * 68;          // [128][68]  Ps[row][key]

    const int tid = threadIdx.x;
    const int tx = tid & 15;
    const int ty = tid >> 4;
    const int bh = blockIdx.y;
    const int bb = bh >> 4;
    const int hh = bh & 15;
    const int q0 = blockIdx.x * 128;

    const float* Qg = g_qkv + (bb * NH + hh) * QKVBLK;
    const float* Kg = Qg + BB * NH * QKVBLK;
    const float* Vg = Kg + BB * NH * QKVBLK;

    // Load Q tile transposed: 128x64 floats, 8 float4 per thread
#pragma unroll
    for (int i = 0; i < 8; i++) {
        int e = i * 1024 + tid * 4;
        int r = e >> 6, d = e & 63;
        float4 v = make_float4(0.f, 0.f, 0.f, 0.f);
        if (q0 + r < NT) v = *(const float4*)(Qg + (q0 + r) * HD + d);
        Qt[(d + 0) * 132 + r] = v.x;
        Qt[(d + 1) * 132 + r] = v.y;
        Qt[(d + 2) * 132 + r] = v.z;
        Qt[(d + 3) * 132 + r] = v.w;
    }

    float m_i[8], l_i[8], oa[8][4];
#pragma unroll
    for (int r = 0; r < 8; r++) {
        m_i[r] = -1e30f;
        l_i[r] = 0.f;
#pragma unroll
        for (int c = 0; c < 4; c++) oa[r][c] = 0.f;
    }

    for (int kt = 0; kt < 25; kt++) {
        const int k0 = kt * 64;
        __syncthreads();   // protect Kt/Vs/Ps (and Qt on first iter)
#pragma unroll
        for (int i = 0; i < 4; i++) {
            int e = i * 1024 + tid * 4;
            int r = e >> 6, d = e & 63;
            float4 kv = make_float4(0.f, 0.f, 0.f, 0.f);
            float4 vv = kv;
            if (k0 + r < NT) {
                kv = *(const float4*)(Kg + (k0 + r) * HD + d);
                vv = *(const float4*)(Vg + (k0 + r) * HD + d);
            }
            Kt[(d + 0) * 68 + r] = kv.x;
            Kt[(d + 1) * 68 + r] = kv.y;
            Kt[(d + 2) * 68 + r] = kv.z;
            Kt[(d + 3) * 68 + r] = kv.w;
            *(float4*)(Vs + r * 68 + d) = vv;
        }
        __syncthreads();

        // S = Q K^T for this tile
        float s[8][4];
#pragma unroll
        for (int r = 0; r < 8; r++)
#pragma unroll
            for (int c = 0; c < 4; c++) s[r][c] = 0.f;

#pragma unroll 8
        for (int d = 0; d < 64; d++) {
            float4 qa = *(const float4*)(Qt + d * 132 + 8 * ty);
            float4 qb = *(const float4*)(Qt + d * 132 + 8 * ty + 4);
            float4 kk = *(const float4*)(Kt + d * 68 + 4 * tx);
            float qv[8] = {qa.x, qa.y, qa.z, qa.w, qb.x, qb.y, qb.z, qb.w};
            float kv4[4] = {kk.x, kk.y, kk.z, kk.w};
#pragma unroll
            for (int r = 0; r < 8; r++)
#pragma unroll
                for (int c = 0; c < 4; c++)
                    s[r][c] = fmaf(qv[r], kv4[c], s[r][c]);
        }

        // Online softmax (row reductions over the 16 tx lanes)
#pragma unroll
        for (int r = 0; r < 8; r++) {
            float mx = -1e30f;
#pragma unroll
            for (int c = 0; c < 4; c++) {
                float v = s[r][c] * 0.125f;
                if (k0 + 4 * tx + c >= NT) v = -1e30f;
                s[r][c] = v;
                mx = fmaxf(mx, v);
            }
            mx = fmaxf(mx, __shfl_xor_sync(0xffffffffu, mx, 1));
            mx = fmaxf(mx, __shfl_xor_sync(0xffffffffu, mx, 2));
            mx = fmaxf(mx, __shfl_xor_sync(0xffffffffu, mx, 4));
            mx = fmaxf(mx, __shfl_xor_sync(0xffffffffu, mx, 8));
            float mn = fmaxf(m_i[r], mx);
            float corr = __expf(m_i[r] - mn);
            m_i[r] = mn;
            float rs = 0.f;
#pragma unroll
            for (int c = 0; c < 4; c++) {
                float p = __expf(s[r][c] - mn);
                s[r][c] = p;
                rs += p;
            }
            rs += __shfl_xor_sync(0xffffffffu, rs, 1);
            rs += __shfl_xor_sync(0xffffffffu, rs, 2);
            rs += __shfl_xor_sync(0xffffffffu, rs, 4);
            rs += __shfl_xor_sync(0xffffffffu, rs, 8);
            l_i[r] = l_i[r] * corr + rs;
#pragma unroll
            for (int c = 0; c < 4; c++) oa[r][c] *= corr;
        }

        // Publish P
#pragma unroll
        for (int r = 0; r < 8; r++)
            *(float4*)(Ps + (8 * ty + r) * 68 + 4 * tx) =
                make_float4(s[r][0], s[r][1], s[r][2], s[r][3]);
        __syncthreads();

        // O += P * V
#pragma unroll 2
        for (int j0 = 0; j0 < 64; j0 += 4) {
            float4 v0 = *(const float4*)(Vs + (j0 + 0) * 68 + 4 * tx);
            float4 v1 = *(const float4*)(Vs + (j0 + 1) * 68 + 4 * tx);
            float4 v2 = *(const float4*)(Vs + (j0 + 2) * 68 + 4 * tx);
            float4 v3 = *(const float4*)(Vs + (j0 + 3) * 68 + 4 * tx);
#pragma unroll
            for (int r = 0; r < 8; r++) {
                float4 pp = *(const float4*)(Ps + (8 * ty + r) * 68 + j0);
                oa[r][0] = fmaf(pp.x, v0.x, oa[r][0]);
                oa[r][1] = fmaf(pp.x, v0.y, oa[r][1]);
                oa[r][2] = fmaf(pp.x, v0.z, oa[r][2]);
                oa[r][3] = fmaf(pp.x, v0.w, oa[r][3]);
                oa[r][0] = fmaf(pp.y, v1.x, oa[r][0]);
                oa[r][1] = fmaf(pp.y, v1.y, oa[r][1]);
                oa[r][2] = fmaf(pp.y, v1.z, oa[r][2]);
                oa[r][3] = fmaf(pp.y, v1.w, oa[r][3]);
                oa[r][0] = fmaf(pp.z, v2.x, oa[r][0]);
                oa[r][1] = fmaf(pp.z, v2.y, oa[r][1]);
                oa[r][2] = fmaf(pp.z, v2.z, oa[r][2]);
                oa[r][3] = fmaf(pp.z, v2.w, oa[r][3]);
                oa[r][0] = fmaf(pp.w, v3.x, oa[r][0]);
                oa[r][1] = fmaf(pp.w, v3.y, oa[r][1]);
                oa[r][2] = fmaf(pp.w, v3.z, oa[r][2]);
                oa[r][3] = fmaf(pp.w, v3.w, oa[r][3]);
            }
        }
    }

    // Normalize and store to [B,N,C] layout
#pragma unroll
    for (int r = 0; r < 8; r++) {
        int n = q0 + 8 * ty + r;
        if (n < NT) {
            float inv = 1.0f / l_i[r];
            float4 ov = make_float4(oa[r][0] * inv, oa[r][1] * inv,
                                    oa[r][2] * inv, oa[r][3] * inv);
            *(float4*)(g_obuf + (bb * NT + n) * CC + hh * HD + 4 * tx) = ov;
        }
    }
}

// ---------------------------------------------------------------------------
extern "C" void kernel_launch(void* const* d_in, const int* in_sizes, int n_in,
                              void* d_out, int out_size) {
    (void)in_sizes; (void)n_in; (void)out_size;
    const float* x = (const float*)d_in[0];
    const float* wqkv = (const float*)d_in[1];
    const float* wproj = (const float*)d_in[2];
    const float* bproj = (const float*)d_in[3];
    float* out = (float*)d_out;

    // Needed once; idempotent and harmless during capture (set on correctness run)
    cudaFuncSetAttribute(attn_k, cudaFuncAttributeMaxDynamicSharedMemorySize, ATTN_SMEM);

    rope_tab_k<<<(NT * 60 + 255) / 256, 256>>>();
    gemm_k<0><<<dim3(24, 49), 256>>>(x, wqkv, nullptr, nullptr);
    attn_k<<<dim3(13, 64), 256, ATTN_SMEM>>>();
    gemm_k<1><<<dim3(8, 49), 256>>>(nullptr, wproj, out, bproj);
}

// round 6
// speedup vs baseline: 1.3659x; 1.3659x over previous
#include <cuda_runtime.h>
#include <cuda_bf16.h>
#include <cstdint>

// Problem constants
#define BB 4
#define NT 1568
#define NH 16
#define HD 64
#define CC 1024
#define MROWS (BB * NT)          // 6272
#define QKVBLK (NT * HD)         // 100352 per (s,b,h)

// ---------------------------------------------------------------------------
// Scratch (device globals — no allocations allowed)
// ---------------------------------------------------------------------------
static __device__ __align__(16) float g_qkv[3 * BB * NH * NT * HD];  // [3][B][H][N][D]
static __device__ __align__(16) float g_obuf[MROWS * CC];            // [B*N][C]
static __device__ __align__(16) float g_ctab[NT * 60];
static __device__ __align__(16) float g_stab[NT * 60];
// bf16 split-precision operand buffers
static __device__ __align__(16) __nv_bfloat16 g_xh[MROWS * CC],  g_xl[MROWS * CC];
static __device__ __align__(16) __nv_bfloat16 g_wqh[3 * CC * CC], g_wql[3 * CC * CC];
static __device__ __align__(16) __nv_bfloat16 g_oh[MROWS * CC],  g_ol[MROWS * CC];
static __device__ __align__(16) __nv_bfloat16 g_wph[CC * CC],    g_wpl[CC * CC];

// ---------------------------------------------------------------------------
// Baseline-PTX tensor helpers (valid for plain sm_100 target: no 'a' features)
// ---------------------------------------------------------------------------
__device__ __forceinline__ uint32_t smem_u32(const void* p) {
    uint32_t a;
    asm("{ .reg .u64 t; cvta.to.shared.u64 t, %1; cvt.u32.u64 %0, t; }" : "=r"(a) : "l"(p));
    return a;
}

__device__ __forceinline__ void ldm4(uint32_t* r, uint32_t addr) {
    asm volatile("ldmatrix.sync.aligned.m8n8.x4.shared.b16 {%0,%1,%2,%3}, [%4];"
                 : "=r"(r[0]), "=r"(r[1]), "=r"(r[2]), "=r"(r[3]) : "r"(addr));
}

__device__ __forceinline__ void mma16816(float* c, const uint32_t* a, const uint32_t* b) {
    asm volatile(
        "mma.sync.aligned.m16n8k16.row.col.f32.bf16.bf16.f32 "
        "{%0,%1,%2,%3}, {%4,%5,%6,%7}, {%8,%9}, {%0,%1,%2,%3};"
        : "+f"(c[0]), "+f"(c[1]), "+f"(c[2]), "+f"(c[3])
        : "r"(a[0]), "r"(a[1]), "r"(a[2]), "r"(a[3]), "r"(b[0]), "r"(b[1]));
}

// ---------------------------------------------------------------------------
// RoPE table: element d (of 60) uses angle = pos_axis(n, d/20) * 10000^{-((d%20)%10)/10}
// (pairs are (2j, 2j+1); cos/sin per-element — validated in R4, rel_err 6.5e-7)
// ---------------------------------------------------------------------------
__global__ void rope_tab_k() {
    int i = blockIdx.x * 256 + threadIdx.x;
    if (i >= NT * 60) return;
    int n = i / 60;
    int d = i - n * 60;
    int axis = d / 20;
    int fi = (d % 20) % 10;
    int fr = n / 196;
    int inf = n - fr * 196;
    int hh = inf / 14;
    int ww = inf - hh * 14;
    float pos = (axis == 0) ? (float)fr : ((axis == 1) ? (float)hh : (float)ww);
    float omega = 1.0f / powf(10000.0f, (float)fi * 0.1f);
    float ang = pos * omega;
    g_ctab[i] = cosf(ang);
    g_stab[i] = sinf(ang);
}

// ---------------------------------------------------------------------------
// fp32 -> (bf16 hi, bf16 lo) split conversion.  which: 0=x, 1=Wqkv, 2=obuf, 3=Wproj
// ---------------------------------------------------------------------------
__global__ void split_k(const float* __restrict__ srcp, int which, int n4) {
    int i = blockIdx.x * 256 + threadIdx.x;
    if (i >= n4) return;
    const float* s = srcp;
    __nv_bfloat16 *h, *l;
    if (which == 0)      { h = g_xh;  l = g_xl;  }
    else if (which == 1) { h = g_wqh; l = g_wql; }
    else if (which == 2) { h = g_oh;  l = g_ol;  s = g_obuf; }
    else                 { h = g_wph; l = g_wpl; }
    float4 v = ((const float4*)s)[i];
    __nv_bfloat16 h0 = __float2bfloat16_rn(v.x);
    __nv_bfloat16 h1 = __float2bfloat16_rn(v.y);
    __nv_bfloat16 h2 = __float2bfloat16_rn(v.z);
    __nv_bfloat16 h3 = __float2bfloat16_rn(v.w);
    __nv_bfloat16 l0 = __float2bfloat16_rn(v.x - __bfloat162float(h0));
    __nv_bfloat16 l1 = __float2bfloat16_rn(v.y - __bfloat162float(h1));
    __nv_bfloat16 l2 = __float2bfloat16_rn(v.z - __bfloat162float(h2));
    __nv_bfloat16 l3 = __float2bfloat16_rn(v.w - __bfloat162float(h3));
    ((__nv_bfloat162*)h)[2 * i]     = __halves2bfloat162(h0, h1);
    ((__nv_bfloat162*)h)[2 * i + 1] = __halves2bfloat162(h2, h3);
    ((__nv_bfloat162*)l)[2 * i]     = __halves2bfloat162(l0, l1);
    ((__nv_bfloat162*)l)[2 * i + 1] = __halves2bfloat162(l2, l3);
}

// ---------------------------------------------------------------------------
// mma.sync bf16 split-precision GEMM: C = A * B^T (both K-major, K=1024).
// Tile 128x128, BK=32, 256 thr = 8 warps (4m x 2n), warp tile 32x64.
// 3 MMAs per operand-pair per K-step: AhBh + AhBl + AlBh (fp32 accum).
// EPI 0: QKV + fused RoPE scatter to g_qkv   (grid 24x49)
// EPI 1: out-projection + bias to Cout       (grid  8x49)
// Smem tiles padded to 40 bf16 (80 B) row stride -> conflict-free ldmatrix.
// ---------------------------------------------------------------------------
#define TILE_B 10240                     // 128 rows * 80 bytes
#define OFF_AH 0
#define OFF_AL (TILE_B)
#define OFF_BH (2 * TILE_B)
#define OFF_BL (3 * TILE_B)

template <int EPI>
__global__ __launch_bounds__(256, 2) void gemm_mma(
    float* __restrict__ Cout, const float* __restrict__ bias)
{
    __shared__ __align__(16) char sm[4 * TILE_B];
    const uint32_t sb = smem_u32(sm);

    const int tid = threadIdx.x;
    const int lane = tid & 31;
    const int wid = tid >> 5;
    const int wm = wid & 3;          // warp row 0..3 (32 rows each)
    const int wn = wid >> 2;         // warp col 0..1 (64 cols each)
    const int bx = blockIdx.x;
    const int by = blockIdx.y;

    const __nv_bfloat16* Agh = (EPI == 0) ? g_xh  : g_oh;
    const __nv_bfloat16* Agl = (EPI == 0) ? g_xl  : g_ol;
    const __nv_bfloat16* Bgh = (EPI == 0) ? g_wqh : g_wph;
    const __nv_bfloat16* Bgl = (EPI == 0) ? g_wql : g_wpl;

    float acc[2][8][4];
#pragma unroll
    for (int mi = 0; mi < 2; mi++)
#pragma unroll
        for (int ni = 0; ni < 8; ni++)
#pragma unroll
            for (int j = 0; j < 4; j++) acc[mi][ni][j] = 0.0f;

    // Loader mapping: thread covers rows (tid>>2) and (tid>>2)+64, chunk (tid&3)*8
    const int lrow = tid >> 2;
    const int lch = tid & 3;

    // ldmatrix source addresses (within-tile byte offsets)
    const uint32_t a_off = (uint32_t)(((wm * 32 + (lane & 15)) * 40 + ((lane >> 4) << 3)) * 2);
    const uint32_t b_off = (uint32_t)(((wn * 64 + (lane & 7) + ((lane >> 4) << 3)) * 40 +
                                      (((lane >> 3) & 1) << 3)) * 2);

#pragma unroll 1
    for (int s = 0; s < 32; s++) {
        const int k0 = s * 32;
        __syncthreads();
#pragma unroll
        for (int hh = 0; hh < 2; hh++) {
            int r = lrow + hh * 64;
            size_t ga = (size_t)(by * 128 + r) * 1024 + k0 + lch * 8;
            size_t gb = (size_t)(bx * 128 + r) * 1024 + k0 + lch * 8;
            uint32_t so = (uint32_t)((r * 40 + lch * 8) * 2);
            *(float4*)(sm + OFF_AH + so) = *(const float4*)(Agh + ga);
            *(float4*)(sm + OFF_AL + so) = *(const float4*)(Agl + ga);
            *(float4*)(sm + OFF_BH + so) = *(const float4*)(Bgh + gb);
            *(float4*)(sm + OFF_BL + so) = *(const float4*)(Bgl + gb);
        }
        __syncthreads();

#pragma unroll
        for (int ks = 0; ks < 2; ks++) {
            const uint32_t kb = (uint32_t)(ks * 16 * 2);   // 16 bf16 along K
            uint32_t ah[2][4], al[2][4];
            ldm4(ah[0], sb + OFF_AH + a_off + kb);
            ldm4(ah[1], sb + OFF_AH + a_off + kb + 16 * 80);
            ldm4(al[0], sb + OFF_AL + a_off + kb);
            ldm4(al[1], sb + OFF_AL + a_off + kb + 16 * 80);
#pragma unroll
            for (int np = 0; np < 4; np++) {
                uint32_t bh[4], bl[4];
                ldm4(bh, sb + OFF_BH + b_off + kb + np * 16 * 80);
                ldm4(bl, sb + OFF_BL + b_off + kb + np * 16 * 80);
#pragma unroll
                for (int mi = 0; mi < 2; mi++) {
                    mma16816(acc[mi][2 * np],     ah[mi], bh);
                    mma16816(acc[mi][2 * np + 1], ah[mi], bh + 2);
                    mma16816(acc[mi][2 * np],     ah[mi], bl);
                    mma16816(acc[mi][2 * np + 1], ah[mi], bl + 2);
                    mma16816(acc[mi][2 * np],     al[mi], bh);
                    mma16816(acc[mi][2 * np + 1], al[mi], bh + 2);
                }
            }
        }
    }

    // Epilogue. Fragment: c0,c1 -> (row g, cols 2t,2t+1); c2,c3 -> (row g+8, same)
    const int g = lane >> 2;
    const int t = lane & 3;
#pragma unroll
    for (int mi = 0; mi < 2; mi++) {
#pragma unroll
        for (int ni = 0; ni < 8; ni++) {
#pragma unroll
            for (int half = 0; half < 2; half++) {
                int rr = wm * 32 + mi * 16 + g + half * 8;
                int o = bx * 128 + wn * 64 + ni * 8 + 2 * t;
                float e = acc[mi][ni][2 * half];
                float oo = acc[mi][ni][2 * half + 1];
                int m = by * 128 + rr;
                if (EPI == 0) {
                    int b = m / NT;
                    int n = m - b * NT;
                    int nb = n * 60;
                    int sidx = o >> 10;
                    int hd = (o & 1023) >> 6;
                    int d = o & 63;
                    float oe = e, of = oo;
                    if (sidx < 2 && d < 60) {
                        float c0 = g_ctab[nb + d],     s0 = g_stab[nb + d];
                        float c1 = g_ctab[nb + d + 1], s1 = g_stab[nb + d + 1];
                        oe = fmaf(e, c0, -oo * s0);
                        of = fmaf(oo, c1, e * s1);
                    }
                    size_t base = (size_t)(((sidx * BB + b) * NH + hd) * NT + n) * 64 + d;
                    *(float2*)&g_qkv[base] = make_float2(oe, of);
                } else {
                    float2 bv = *(const float2*)&bias[o];
                    *(float2*)&Cout[(size_t)m * CC + o] = make_float2(e + bv.x, oo + bv.y);
                }
            }
        }
    }
}

// ---------------------------------------------------------------------------
// Flash attention (fp32 SIMT, verified in R4): grid (13, 64). BQ=128, BK=64.
// ---------------------------------------------------------------------------
#define ATTN_SMEM ((64 * 132 + 64 * 68 + 64 * 68 + 128 * 68) * 4)

__global__ __launch_bounds__(256, 2) void attn_k() {
    extern __shared__ float smf[];
    float* Qt = smf;                   // [64][132]
    float* Kt = Qt + 64 * 132;         // [64][68]
    float* Vs = Kt + 64 * 68;          // [64][68]
    float* Ps = Vs + 64 * 68;          // [128][68]

    const int tid = threadIdx.x;
    const int tx = tid & 15;
    const int ty = tid >> 4;
    const int bh = blockIdx.y;
    const int bb = bh >> 4;
    const int hh = bh & 15;
    const int q0 = blockIdx.x * 128;

    const float* Qg = g_qkv + (bb * NH + hh) * QKVBLK;
    const float* Kg = Qg + BB * NH * QKVBLK;
    const float* Vg = Kg + BB * NH * QKVBLK;

#pragma unroll
    for (int i = 0; i < 8; i++) {
        int e = i * 1024 + tid * 4;
        int r = e >> 6, d = e & 63;
        float4 v = make_float4(0.f, 0.f, 0.f, 0.f);
        if (q0 + r < NT) v = *(const float4*)(Qg + (q0 + r) * HD + d);
        Qt[(d + 0) * 132 + r] = v.x;
        Qt[(d + 1) * 132 + r] = v.y;
        Qt[(d + 2) * 132 + r] = v.z;
        Qt[(d + 3) * 132 + r] = v.w;
    }

    float m_i[8], l_i[8], oa[8][4];
#pragma unroll
    for (int r = 0; r < 8; r++) {
        m_i[r] = -1e30f;
        l_i[r] = 0.f;
#pragma unroll
        for (int c = 0; c < 4; c++) oa[r][c] = 0.f;
    }

    for (int kt = 0; kt < 25; kt++) {
        const int k0 = kt * 64;
        __syncthreads();
#pragma unroll
        for (int i = 0; i < 4; i++) {
            int e = i * 1024 + tid * 4;
            int r = e >> 6, d = e & 63;
            float4 kv = make_float4(0.f, 0.f, 0.f, 0.f);
            float4 vv = kv;
            if (k0 + r < NT) {
                kv = *(const float4*)(Kg + (k0 + r) * HD + d);
                vv = *(const float4*)(Vg + (k0 + r) * HD + d);
            }
            Kt[(d + 0) * 68 + r] = kv.x;
            Kt[(d + 1) * 68 + r] = kv.y;
            Kt[(d + 2) * 68 + r] = kv.z;
            Kt[(d + 3) * 68 + r] = kv.w;
            *(float4*)(Vs + r * 68 + d) = vv;
        }
        __syncthreads();

        float s[8][4];
#pragma unroll
        for (int r = 0; r < 8; r++)
#pragma unroll
            for (int c = 0; c < 4; c++) s[r][c] = 0.f;

#pragma unroll 8
        for (int d = 0; d < 64; d++) {
            float4 qa = *(const float4*)(Qt + d * 132 + 8 * ty);
            float4 qb = *(const float4*)(Qt + d * 132 + 8 * ty + 4);
            float4 kk = *(const float4*)(Kt + d * 68 + 4 * tx);
            float qv[8] = {qa.x, qa.y, qa.z, qa.w, qb.x, qb.y, qb.z, qb.w};
            float kv4[4] = {kk.x, kk.y, kk.z, kk.w};
#pragma unroll
            for (int r = 0; r < 8; r++)
#pragma unroll
                for (int c = 0; c < 4; c++)
                    s[r][c] = fmaf(qv[r], kv4[c], s[r][c]);
        }

#pragma unroll
        for (int r = 0; r < 8; r++) {
            float mx = -1e30f;
#pragma unroll
            for (int c = 0; c < 4; c++) {
                float v = s[r][c] * 0.125f;
                if (k0 + 4 * tx + c >= NT) v = -1e30f;
                s[r][c] = v;
                mx = fmaxf(mx, v);
            }
            mx = fmaxf(mx, __shfl_xor_sync(0xffffffffu, mx, 1));
            mx = fmaxf(mx, __shfl_xor_sync(0xffffffffu, mx, 2));
            mx = fmaxf(mx, __shfl_xor_sync(0xffffffffu, mx, 4));
            mx = fmaxf(mx, __shfl_xor_sync(0xffffffffu, mx, 8));
            float mn = fmaxf(m_i[r], mx);
            float corr = __expf(m_i[r] - mn);
            m_i[r] = mn;
            float rs = 0.f;
#pragma unroll
            for (int c = 0; c < 4; c++) {
                float p = __expf(s[r][c] - mn);
                s[r][c] = p;
                rs += p;
            }
            rs += __shfl_xor_sync(0xffffffffu, rs, 1);
            rs += __shfl_xor_sync(0xffffffffu, rs, 2);
            rs += __shfl_xor_sync(0xffffffffu, rs, 4);
            rs += __shfl_xor_sync(0xffffffffu, rs, 8);
            l_i[r] = l_i[r] * corr + rs;
#pragma unroll
            for (int c = 0; c < 4; c++) oa[r][c] *= corr;
        }

#pragma unroll
        for (int r = 0; r < 8; r++)
            *(float4*)(Ps + (8 * ty + r) * 68 + 4 * tx) =
                make_float4(s[r][0], s[r][1], s[r][2], s[r][3]);
        __syncthreads();

#pragma unroll 2
        for (int j0 = 0; j0 < 64; j0 += 4) {
            float4 v0 = *(const float4*)(Vs + (j0 + 0) * 68 + 4 * tx);
            float4 v1 = *(const float4*)(Vs + (j0 + 1) * 68 + 4 * tx);
            float4 v2 = *(const float4*)(Vs + (j0 + 2) * 68 + 4 * tx);
            float4 v3 = *(const float4*)(Vs + (j0 + 3) * 68 + 4 * tx);
#pragma unroll
            for (int r = 0; r < 8; r++) {
                float4 pp = *(const float4*)(Ps + (8 * ty + r) * 68 + j0);
                oa[r][0] = fmaf(pp.x, v0.x, oa[r][0]);
                oa[r][1] = fmaf(pp.x, v0.y, oa[r][1]);
                oa[r][2] = fmaf(pp.x, v0.z, oa[r][2]);
                oa[r][3] = fmaf(pp.x, v0.w, oa[r][3]);
                oa[r][0] = fmaf(pp.y, v1.x, oa[r][0]);
                oa[r][1] = fmaf(pp.y, v1.y, oa[r][1]);
                oa[r][2] = fmaf(pp.y, v1.z, oa[r][2]);
                oa[r][3] = fmaf(pp.y, v1.w, oa[r][3]);
                oa[r][0] = fmaf(pp.z, v2.x, oa[r][0]);
                oa[r][1] = fmaf(pp.z, v2.y, oa[r][1]);
                oa[r][2] = fmaf(pp.z, v2.z, oa[r][2]);
                oa[r][3] = fmaf(pp.z, v2.w, oa[r][3]);
                oa[r][0] = fmaf(pp.w, v3.x, oa[r][0]);
                oa[r][1] = fmaf(pp.w, v3.y, oa[r][1]);
                oa[r][2] = fmaf(pp.w, v3.z, oa[r][2]);
                oa[r][3] = fmaf(pp.w, v3.w, oa[r][3]);
            }
        }
    }

#pragma unroll
    for (int r = 0; r < 8; r++) {
        int n = q0 + 8 * ty + r;
        if (n < NT) {
            float inv = 1.0f / l_i[r];
            float4 ov = make_float4(oa[r][0] * inv, oa[r][1] * inv,
                                    oa[r][2] * inv, oa[r][3] * inv);
            *(float4*)(g_obuf + (bb * NT + n) * CC + hh * HD + 4 * tx) = ov;
        }
    }
}

// ---------------------------------------------------------------------------
extern "C" void kernel_launch(void* const* d_in, const int* in_sizes, int n_in,
                              void* d_out, int out_size) {
    (void)in_sizes; (void)n_in; (void)out_size;
    const float* x = (const float*)d_in[0];
    const float* wqkv = (const float*)d_in[1];
    const float* wproj = (const float*)d_in[2];
    const float* bproj = (const float*)d_in[3];
    float* out = (float*)d_out;

    cudaFuncSetAttribute(attn_k, cudaFuncAttributeMaxDynamicSharedMemorySize, ATTN_SMEM);

    rope_tab_k<<<(NT * 60 + 255) / 256, 256>>>();

    int n4x = MROWS * CC / 4;
    int n4w = 3 * CC * CC / 4;
    int n4p = CC * CC / 4;
    split_k<<<(n4x + 255) / 256, 256>>>(x, 0, n4x);
    split_k<<<(n4w + 255) / 256, 256>>>(wqkv, 1, n4w);
    split_k<<<(n4p + 255) / 256, 256>>>(wproj, 3, n4p);

    gemm_mma<0><<<dim3(24, 49), 256>>>(nullptr, nullptr);
    attn_k<<<dim3(13, 64), 256, ATTN_SMEM>>>();
    split_k<<<(n4x + 255) / 256, 256>>>(nullptr, 2, n4x);
    gemm_mma<1><<<dim3(8, 49), 256>>>(out, bproj);
}

// round 7
// speedup vs baseline: 2.3493x; 1.7200x over previous
#include <cuda_runtime.h>
#include <cuda_bf16.h>
#include <cstdint>

// Problem constants
#define BB 4
#define NT 1568
#define NH 16
#define HD 64
#define CC 1024
#define MROWS (BB * NT)          // 6272

// ---------------------------------------------------------------------------
// Scratch (device globals — no allocations allowed)
// ---------------------------------------------------------------------------
static __device__ __align__(16) float g_ctab[NT * 60];
static __device__ __align__(16) float g_stab[NT * 60];
// split-precision operand buffers
static __device__ __align__(16) __nv_bfloat16 g_xh[MROWS * CC],  g_xl[MROWS * CC];
static __device__ __align__(16) __nv_bfloat16 g_wqh[3 * CC * CC], g_wql[3 * CC * CC];
static __device__ __align__(16) __nv_bfloat16 g_wph[CC * CC],    g_wpl[CC * CC];
// q/k/v split buffers, layout [B][H][N][64]
#define QKVN (BB * NH * NT * HD)
static __device__ __align__(16) __nv_bfloat16 g_qh[QKVN], g_ql[QKVN];
static __device__ __align__(16) __nv_bfloat16 g_kh[QKVN], g_kl[QKVN];
static __device__ __align__(16) __nv_bfloat16 g_vh[QKVN], g_vl[QKVN];
// attention output split, layout [B*N][C]
static __device__ __align__(16) __nv_bfloat16 g_oh[MROWS * CC], g_ol[MROWS * CC];

// ---------------------------------------------------------------------------
// Baseline-PTX tensor helpers (plain sm_100 target: no 'a'-suffix features)
// ---------------------------------------------------------------------------
__device__ __forceinline__ uint32_t smem_u32(const void* p) {
    uint32_t a;
    asm("{ .reg .u64 t; cvta.to.shared.u64 t, %1; cvt.u32.u64 %0, t; }" : "=r"(a) : "l"(p));
    return a;
}
__device__ __forceinline__ void ldm4(uint32_t* r, uint32_t addr) {
    asm volatile("ldmatrix.sync.aligned.m8n8.x4.shared.b16 {%0,%1,%2,%3}, [%4];"
                 : "=r"(r[0]), "=r"(r[1]), "=r"(r[2]), "=r"(r[3]) : "r"(addr));
}
__device__ __forceinline__ void ldm4t(uint32_t* r, uint32_t addr) {
    asm volatile("ldmatrix.sync.aligned.m8n8.x4.trans.shared.b16 {%0,%1,%2,%3}, [%4];"
                 : "=r"(r[0]), "=r"(r[1]), "=r"(r[2]), "=r"(r[3]) : "r"(addr));
}
__device__ __forceinline__ void mma16816(float* c, const uint32_t* a, const uint32_t* b) {
    asm volatile(
        "mma.sync.aligned.m16n8k16.row.col.f32.bf16.bf16.f32 "
        "{%0,%1,%2,%3}, {%4,%5,%6,%7}, {%8,%9}, {%0,%1,%2,%3};"
        : "+f"(c[0]), "+f"(c[1]), "+f"(c[2]), "+f"(c[3])
        : "r"(a[0]), "r"(a[1]), "r"(a[2]), "r"(a[3]), "r"(b[0]), "r"(b[1]));
}
__device__ __forceinline__ uint32_t pack_hi(float a, float b) {
    __nv_bfloat162 v = __halves2bfloat162(__float2bfloat16_rn(a), __float2bfloat16_rn(b));
    return *(uint32_t*)&v;
}
__device__ __forceinline__ uint32_t pack_lo(float a, float b) {
    __nv_bfloat16 ha = __float2bfloat16_rn(a), hb = __float2bfloat16_rn(b);
    __nv_bfloat162 v = __halves2bfloat162(
        __float2bfloat16_rn(a - __bfloat162float(ha)),
        __float2bfloat16_rn(b - __bfloat162float(hb)));
    return *(uint32_t*)&v;
}

// ---------------------------------------------------------------------------
// RoPE table (validated R4/R6)
// ---------------------------------------------------------------------------
__global__ void rope_tab_k() {
    int i = blockIdx.x * 256 + threadIdx.x;
    if (i >= NT * 60) return;
    int n = i / 60;
    int d = i - n * 60;
    int axis = d / 20;
    int fi = (d % 20) % 10;
    int fr = n / 196;
    int inf = n - fr * 196;
    int hh = inf / 14;
    int ww = inf - hh * 14;
    float pos = (axis == 0) ? (float)fr : ((axis == 1) ? (float)hh : (float)ww);
    float omega = 1.0f / powf(10000.0f, (float)fi * 0.1f);
    g_ctab[i] = cosf(pos * omega);
    g_stab[i] = sinf(pos * omega);
}

// ---------------------------------------------------------------------------
// fp32 -> (bf16 hi, bf16 lo).  which: 0=x, 1=Wqkv, 2=Wproj
// ---------------------------------------------------------------------------
__global__ void split_k(const float* __restrict__ s, int which, int n4) {
    int i = blockIdx.x * 256 + threadIdx.x;
    if (i >= n4) return;
    __nv_bfloat16 *h, *l;
    if (which == 0)      { h = g_xh;  l = g_xl;  }
    else if (which == 1) { h = g_wqh; l = g_wql; }
    else                 { h = g_wph; l = g_wpl; }
    float4 v = ((const float4*)s)[i];
    ((uint32_t*)h)[2 * i]     = pack_hi(v.x, v.y);
    ((uint32_t*)h)[2 * i + 1] = pack_hi(v.z, v.w);
    ((uint32_t*)l)[2 * i]     = pack_lo(v.x, v.y);
    ((uint32_t*)l)[2 * i + 1] = pack_lo(v.z, v.w);
}

// ---------------------------------------------------------------------------
// mma.sync bf16 split GEMM: C = A * B^T (K-major, K=1024). Validated R6.
// EPI 0: QKV + RoPE, emit bf16 hi/lo q/k/v (q pre-scaled by 1/8). grid 24x49
// EPI 1: out-projection + bias to Cout.                           grid  8x49
// ---------------------------------------------------------------------------
#define TILE_B 10240
#define OFF_AH 0
#define OFF_AL (TILE_B)
#define OFF_BH (2 * TILE_B)
#define OFF_BL (3 * TILE_B)

template <int EPI>
__global__ __launch_bounds__(256, 2) void gemm_mma(
    float* __restrict__ Cout, const float* __restrict__ bias)
{
    __shared__ __align__(16) char sm[4 * TILE_B];
    const uint32_t sb = smem_u32(sm);

    const int tid = threadIdx.x;
    const int lane = tid & 31;
    const int wid = tid >> 5;
    const int wm = wid & 3;
    const int wn = wid >> 2;
    const int bx = blockIdx.x;
    const int by = blockIdx.y;

    const __nv_bfloat16* Agh = (EPI == 0) ? g_xh  : g_oh;
    const __nv_bfloat16* Agl = (EPI == 0) ? g_xl  : g_ol;
    const __nv_bfloat16* Bgh = (EPI == 0) ? g_wqh : g_wph;
    const __nv_bfloat16* Bgl = (EPI == 0) ? g_wql : g_wpl;

    float acc[2][8][4];
#pragma unroll
    for (int mi = 0; mi < 2; mi++)
#pragma unroll
        for (int ni = 0; ni < 8; ni++)
#pragma unroll
            for (int j = 0; j < 4; j++) acc[mi][ni][j] = 0.0f;

    const int lrow = tid >> 2;
    const int lch = tid & 3;
    const uint32_t a_off = (uint32_t)(((wm * 32 + (lane & 15)) * 40 + ((lane >> 4) << 3)) * 2);
    const uint32_t b_off = (uint32_t)(((wn * 64 + (lane & 7) + ((lane >> 4) << 3)) * 40 +
                                      (((lane >> 3) & 1) << 3)) * 2);

#pragma unroll 1
    for (int s = 0; s < 32; s++) {
        const int k0 = s * 32;
        __syncthreads();
#pragma unroll
        for (int hh = 0; hh < 2; hh++) {
            int r = lrow + hh * 64;
            size_t ga = (size_t)(by * 128 + r) * 1024 + k0 + lch * 8;
            size_t gb = (size_t)(bx * 128 + r) * 1024 + k0 + lch * 8;
            uint32_t so = (uint32_t)((r * 40 + lch * 8) * 2);
            *(float4*)(sm + OFF_AH + so) = *(const float4*)(Agh + ga);
            *(float4*)(sm + OFF_AL + so) = *(const float4*)(Agl + ga);
            *(float4*)(sm + OFF_BH + so) = *(const float4*)(Bgh + gb);
            *(float4*)(sm + OFF_BL + so) = *(const float4*)(Bgl + gb);
        }
        __syncthreads();

#pragma unroll
        for (int ks = 0; ks < 2; ks++) {
            const uint32_t kb = (uint32_t)(ks * 32);
            uint32_t ah[2][4], al[2][4];
            ldm4(ah[0], sb + OFF_AH + a_off + kb);
            ldm4(ah[1], sb + OFF_AH + a_off + kb + 16 * 80);
            ldm4(al[0], sb + OFF_AL + a_off + kb);
            ldm4(al[1], sb + OFF_AL + a_off + kb + 16 * 80);
#pragma unroll
            for (int np = 0; np < 4; np++) {
                uint32_t bh[4], bl[4];
                ldm4(bh, sb + OFF_BH + b_off + kb + np * 16 * 80);
                ldm4(bl, sb + OFF_BL + b_off + kb + np * 16 * 80);
#pragma unroll
                for (int mi = 0; mi < 2; mi++) {
                    mma16816(acc[mi][2 * np],     ah[mi], bh);
                    mma16816(acc[mi][2 * np + 1], ah[mi], bh + 2);
                    mma16816(acc[mi][2 * np],     ah[mi], bl);
                    mma16816(acc[mi][2 * np + 1], ah[mi], bl + 2);
                    mma16816(acc[mi][2 * np],     al[mi], bh);
                    mma16816(acc[mi][2 * np + 1], al[mi], bh + 2);
                }
            }
        }
    }

    const int g = lane >> 2;
    const int t = lane & 3;
#pragma unroll
    for (int mi = 0; mi < 2; mi++) {
#pragma unroll
        for (int ni = 0; ni < 8; ni++) {
#pragma unroll
            for (int half = 0; half < 2; half++) {
                int rr = wm * 32 + mi * 16 + g + half * 8;
                int o = bx * 128 + wn * 64 + ni * 8 + 2 * t;
                float e = acc[mi][ni][2 * half];
                float oo = acc[mi][ni][2 * half + 1];
                int m = by * 128 + rr;
                if (EPI == 0) {
                    int b = m / NT;
                    int n = m - b * NT;
                    int nb = n * 60;
                    int sidx = o >> 10;
                    int hd = (o & 1023) >> 6;
                    int d = o & 63;
                    float oe = e, of = oo;
                    if (sidx < 2 && d < 60) {
                        float c0 = g_ctab[nb + d],     s0 = g_stab[nb + d];
                        float c1 = g_ctab[nb + d + 1], s1 = g_stab[nb + d + 1];
                        oe = fmaf(e, c0, -oo * s0);
                        of = fmaf(oo, c1, e * s1);
                    }
                    if (sidx == 0) { oe *= 0.125f; of *= 0.125f; }  // fold softmax scale
                    __nv_bfloat16 *dh, *dl;
                    if (sidx == 0)      { dh = g_qh; dl = g_ql; }
                    else if (sidx == 1) { dh = g_kh; dl = g_kl; }
                    else                { dh = g_vh; dl = g_vl; }
                    size_t base = ((size_t)((b * NH + hd) * NT + n)) * 64 + d;
                    *(uint32_t*)&dh[base] = pack_hi(oe, of);
                    *(uint32_t*)&dl[base] = pack_lo(oe, of);
                } else {
                    float2 bv = *(const float2*)&bias[o];
                    *(float2*)&Cout[(size_t)m * CC + o] = make_float2(e + bv.x, oo + bv.y);
                }
            }
        }
    }
}

// ---------------------------------------------------------------------------
// Tensor-core flash attention. grid (13 q-tiles, 64 bh). BQ=128, BK=64.
// 256 thr = 8 warps, warp w owns q rows 16w..16w+15, full d=64 output.
// Split-bf16: S = QhKh+QhKl+QlKh;  O += PhVh+PhVl+PlVh.  Smem stride 72 bf16.
// ---------------------------------------------------------------------------
#define AST 72
#define SQ_H 0
#define SQ_L (128 * AST)
#define SK_H (2 * 128 * AST)
#define SK_L (SK_H + 64 * AST)
#define SV_H (SK_H + 2 * 64 * AST)
#define SV_L (SK_H + 3 * 64 * AST)
#define ATTN_SMEM ((2 * 128 * AST + 4 * 64 * AST) * 2)   // 73728 bytes

__global__ __launch_bounds__(256) void attn_k() {
    extern __shared__ __nv_bfloat16 smb[];
    const uint32_t sb = smem_u32(smb);

    const int tid = threadIdx.x;
    const int lane = tid & 31;
    const int wid = tid >> 5;
    const int g = lane >> 2;
    const int t = lane & 3;
    const int bh = blockIdx.y;
    const int bb = bh >> 4;
    const int hh = bh & 15;
    const int q0 = blockIdx.x * 128;

    const size_t hb = (size_t)(bb * NH + hh) * NT * 64;

    // Load Q tile (hi & lo): 128 rows x 64, 4 float4 per thread per operand
#pragma unroll
    for (int i = 0; i < 4; i++) {
        int idx = i * 256 + tid;
        int r = idx >> 3, c = idx & 7;
        int gr = q0 + r;
        float4 vh = make_float4(0.f, 0.f, 0.f, 0.f), vl = vh;
        if (gr < NT) {
            vh = ((const float4*)(g_qh + hb + (size_t)gr * 64))[c];
            vl = ((const float4*)(g_ql + hb + (size_t)gr * 64))[c];
        }
        *(float4*)(smb + SQ_H + r * AST + c * 8) = vh;
        *(float4*)(smb + SQ_L + r * AST + c * 8) = vl;
    }

    float oacc[8][4];
#pragma unroll
    for (int nd = 0; nd < 8; nd++)
#pragma unroll
        for (int j = 0; j < 4; j++) oacc[nd][j] = 0.f;
    float m2[2] = {-1e30f, -1e30f};
    float l2[2] = {0.f, 0.f};

    const uint32_t a_base = sb + 2 * (uint32_t)((wid * 16 + (lane & 15)) * AST + ((lane >> 4) << 3));
    const uint32_t b_roff = (uint32_t)((lane & 7) + ((lane >> 4) << 3));
    const uint32_t b_coff = (uint32_t)(((lane >> 3) & 1) << 3);
    const uint32_t v_roff = (uint32_t)(lane & 15);
    const uint32_t v_coff = (uint32_t)((lane >> 4) << 3);

#pragma unroll 1
    for (int kt = 0; kt < 25; kt++) {
        const int k0 = kt * 64;
        __syncthreads();
#pragma unroll
        for (int i = 0; i < 2; i++) {
            int idx = i * 256 + tid;
            int r = idx >> 3, c = idx & 7;
            int gr = k0 + r;
            float4 kh = make_float4(0.f, 0.f, 0.f, 0.f), kl = kh, vh = kh, vl = kh;
            if (gr < NT) {
                kh = ((const float4*)(g_kh + hb + (size_t)gr * 64))[c];
                kl = ((const float4*)(g_kl + hb + (size_t)gr * 64))[c];
                vh = ((const float4*)(g_vh + hb + (size_t)gr * 64))[c];
                vl = ((const float4*)(g_vl + hb + (size_t)gr * 64))[c];
            }
            *(float4*)(smb + SK_H + r * AST + c * 8) = kh;
            *(float4*)(smb + SK_L + r * AST + c * 8) = kl;
            *(float4*)(smb + SV_H + r * AST + c * 8) = vh;
            *(float4*)(smb + SV_L + r * AST + c * 8) = vl;
        }
        __syncthreads();

        // S = Q K^T (3-way split), 8 n8 tiles x m16
        float sacc[8][4];
#pragma unroll
        for (int ni = 0; ni < 8; ni++)
#pragma unroll
            for (int j = 0; j < 4; j++) sacc[ni][j] = 0.f;

#pragma unroll
        for (int ds = 0; ds < 4; ds++) {
            uint32_t qh4[4], ql4[4];
            ldm4(qh4, a_base + 2 * (uint32_t)(ds * 16));
            ldm4(ql4, a_base + 2 * (uint32_t)(128 * AST + ds * 16));
#pragma unroll
            for (int ng = 0; ng < 4; ng++) {
                uint32_t kh4[4], kl4[4];
                uint32_t be = 2 * (uint32_t)((ng * 16 + b_roff) * AST + ds * 16 + b_coff);
                ldm4(kh4, sb + SK_H * 2 + be);
                ldm4(kl4, sb + SK_L * 2 + be);
                mma16816(sacc[2 * ng],     qh4, kh4);
                mma16816(sacc[2 * ng + 1], qh4, kh4 + 2);
                mma16816(sacc[2 * ng],     qh4, kl4);
                mma16816(sacc[2 * ng + 1], qh4, kl4 + 2);
                mma16816(sacc[2 * ng],     ql4, kh4);
                mma16816(sacc[2 * ng + 1], ql4, kh4 + 2);
            }
        }

        // Online softmax (per lane: row g uses c0/c1, row g+8 uses c2/c3)
        const bool tail = (k0 + 64 > NT);
        if (tail) {
#pragma unroll
            for (int ni = 0; ni < 8; ni++) {
                int c0 = k0 + 8 * ni + 2 * t;
                if (c0 >= NT)     { sacc[ni][0] = -1e30f; sacc[ni][2] = -1e30f; }
                if (c0 + 1 >= NT) { sacc[ni][1] = -1e30f; sacc[ni][3] = -1e30f; }
            }
        }
#pragma unroll
        for (int h2 = 0; h2 < 2; h2++) {
            float mx = -1e30f;
#pragma unroll
            for (int ni = 0; ni < 8; ni++)
                mx = fmaxf(mx, fmaxf(sacc[ni][2 * h2], sacc[ni][2 * h2 + 1]));
            mx = fmaxf(mx, __shfl_xor_sync(0xffffffffu, mx, 1));
            mx = fmaxf(mx, __shfl_xor_sync(0xffffffffu, mx, 2));
            float mn = fmaxf(m2[h2], mx);
            float corr = __expf(m2[h2] - mn);
            m2[h2] = mn;
            float rs = 0.f;
#pragma unroll
            for (int ni = 0; ni < 8; ni++) {
                float p0 = __expf(sacc[ni][2 * h2] - mn);
                float p1 = __expf(sacc[ni][2 * h2 + 1] - mn);
                sacc[ni][2 * h2] = p0;
                sacc[ni][2 * h2 + 1] = p1;
                rs += p0 + p1;
            }
            rs += __shfl_xor_sync(0xffffffffu, rs, 1);
            rs += __shfl_xor_sync(0xffffffffu, rs, 2);
            l2[h2] = l2[h2] * corr + rs;
#pragma unroll
            for (int nd = 0; nd < 8; nd++) {
                oacc[nd][2 * h2] *= corr;
                oacc[nd][2 * h2 + 1] *= corr;
            }
        }

        // O += P V (3-way split). P frags built in-register from sacc.
#pragma unroll
        for (int kc = 0; kc < 4; kc++) {
            uint32_t ph[4], pl[4];
            ph[0] = pack_hi(sacc[2 * kc][0], sacc[2 * kc][1]);
            ph[1] = pack_hi(sacc[2 * kc][2], sacc[2 * kc][3]);
            ph[2] = pack_hi(sacc[2 * kc + 1][0], sacc[2 * kc + 1][1]);
            ph[3] = pack_hi(sacc[2 * kc + 1][2], sacc[2 * kc + 1][3]);
            pl[0] = pack_lo(sacc[2 * kc][0], sacc[2 * kc][1]);
            pl[1] = pack_lo(sacc[2 * kc][2], sacc[2 * kc][3]);
            pl[2] = pack_lo(sacc[2 * kc + 1][0], sacc[2 * kc + 1][1]);
            pl[3] = pack_lo(sacc[2 * kc + 1][2], sacc[2 * kc + 1][3]);
#pragma unroll
            for (int dg = 0; dg < 4; dg++) {
                uint32_t vh4[4], vl4[4];
                uint32_t ve = 2 * (uint32_t)((kc * 16 + v_roff) * AST + dg * 16 + v_coff);
                ldm4t(vh4, sb + SV_H * 2 + ve);
                ldm4t(vl4, sb + SV_L * 2 + ve);
                mma16816(oacc[2 * dg],     ph, vh4);
                mma16816(oacc[2 * dg + 1], ph, vh4 + 2);
                mma16816(oacc[2 * dg],     ph, vl4);
                mma16816(oacc[2 * dg + 1], ph, vl4 + 2);
                mma16816(oacc[2 * dg],     pl, vh4);
                mma16816(oacc[2 * dg + 1], pl, vh4 + 2);
            }
        }
    }

    // Normalize, split to bf16 hi/lo, store to [B*N][C]
#pragma unroll
    for (int h2 = 0; h2 < 2; h2++) {
        int r = q0 + wid * 16 + g + 8 * h2;
        if (r < NT) {
            float inv = 1.0f / l2[h2];
            size_t ob = (size_t)(bb * NT + r) * CC + hh * 64;
#pragma unroll
            for (int nd = 0; nd < 8; nd++) {
                int col = 8 * nd + 2 * t;
                float o0 = oacc[nd][2 * h2] * inv;
                float o1 = oacc[nd][2 * h2 + 1] * inv;
                *(uint32_t*)&g_oh[ob + col] = pack_hi(o0, o1);
                *(uint32_t*)&g_ol[ob + col] = pack_lo(o0, o1);
            }
        }
    }
}

// ---------------------------------------------------------------------------
extern "C" void kernel_launch(void* const* d_in, const int* in_sizes, int n_in,
                              void* d_out, int out_size) {
    (void)in_sizes; (void)n_in; (void)out_size;
    const float* x = (const float*)d_in[0];
    const float* wqkv = (const float*)d_in[1];
    const float* wproj = (const float*)d_in[2];
    const float* bproj = (const float*)d_in[3];
    float* out = (float*)d_out;

    cudaFuncSetAttribute(attn_k, cudaFuncAttributeMaxDynamicSharedMemorySize, ATTN_SMEM);

    rope_tab_k<<<(NT * 60 + 255) / 256, 256>>>();

    int n4x = MROWS * CC / 4;
    int n4w = 3 * CC * CC / 4;
    int n4p = CC * CC / 4;
    split_k<<<(n4x + 255) / 256, 256>>>(x, 0, n4x);
    split_k<<<(n4w + 255) / 256, 256>>>(wqkv, 1, n4w);
    split_k<<<(n4p + 255) / 256, 256>>>(wproj, 2, n4p);

    gemm_mma<0><<<dim3(24, 49), 256>>>(nullptr, nullptr);
    attn_k<<<dim3(13, 64), 256, ATTN_SMEM>>>();
    gemm_mma<1><<<dim3(8, 49), 256>>>(out, bproj);
}

// round 8
// speedup vs baseline: 2.5643x; 1.0915x over previous
#include <cuda_runtime.h>
#include <cuda_bf16.h>
#include <cstdint>

// Problem constants
#define BB 4
#define NT 1568
#define NH 16
#define HD 64
#define CC 1024
#define MROWS (BB * NT)          // 6272

// ---------------------------------------------------------------------------
// Scratch (device globals — no allocations allowed)
// ---------------------------------------------------------------------------
static __device__ __align__(16) float g_ctab[NT * 60];
static __device__ __align__(16) float g_stab[NT * 60];
static __device__ __align__(16) __nv_bfloat16 g_xh[MROWS * CC],  g_xl[MROWS * CC];
static __device__ __align__(16) __nv_bfloat16 g_wqh[3 * CC * CC], g_wql[3 * CC * CC];
static __device__ __align__(16) __nv_bfloat16 g_wph[CC * CC],    g_wpl[CC * CC];
#define QKVN (BB * NH * NT * HD)
static __device__ __align__(16) __nv_bfloat16 g_qh[QKVN], g_ql[QKVN];
static __device__ __align__(16) __nv_bfloat16 g_kh[QKVN], g_kl[QKVN];
static __device__ __align__(16) __nv_bfloat16 g_vh[QKVN], g_vl[QKVN];
static __device__ __align__(16) __nv_bfloat16 g_oh[MROWS * CC], g_ol[MROWS * CC];

// ---------------------------------------------------------------------------
// Baseline-PTX helpers (plain sm_100 target)
// ---------------------------------------------------------------------------
__device__ __forceinline__ uint32_t smem_u32(const void* p) {
    uint32_t a;
    asm("{ .reg .u64 t; cvta.to.shared.u64 t, %1; cvt.u32.u64 %0, t; }" : "=r"(a) : "l"(p));
    return a;
}
__device__ __forceinline__ void ldm4(uint32_t* r, uint32_t addr) {
    asm volatile("ldmatrix.sync.aligned.m8n8.x4.shared.b16 {%0,%1,%2,%3}, [%4];"
                 : "=r"(r[0]), "=r"(r[1]), "=r"(r[2]), "=r"(r[3]) : "r"(addr));
}
__device__ __forceinline__ void ldm4t(uint32_t* r, uint32_t addr) {
    asm volatile("ldmatrix.sync.aligned.m8n8.x4.trans.shared.b16 {%0,%1,%2,%3}, [%4];"
                 : "=r"(r[0]), "=r"(r[1]), "=r"(r[2]), "=r"(r[3]) : "r"(addr));
}
__device__ __forceinline__ void mma16816(float* c, const uint32_t* a, const uint32_t* b) {
    asm volatile(
        "mma.sync.aligned.m16n8k16.row.col.f32.bf16.bf16.f32 "
        "{%0,%1,%2,%3}, {%4,%5,%6,%7}, {%8,%9}, {%0,%1,%2,%3};"
        : "+f"(c[0]), "+f"(c[1]), "+f"(c[2]), "+f"(c[3])
        : "r"(a[0]), "r"(a[1]), "r"(a[2]), "r"(a[3]), "r"(b[0]), "r"(b[1]));
}
__device__ __forceinline__ void cp16(uint32_t s, const void* g) {
    asm volatile("cp.async.cg.shared.global [%0], [%1], 16;" :: "r"(s), "l"(g));
}
__device__ __forceinline__ void cp16z(uint32_t s, const void* g, int sz) {
    asm volatile("cp.async.cg.shared.global [%0], [%1], 16, %2;" :: "r"(s), "l"(g), "r"(sz));
}
#define CP_COMMIT() asm volatile("cp.async.commit_group;" ::: "memory")
#define CP_WAIT(n)  asm volatile("cp.async.wait_group %0;" :: "n"(n) : "memory")

__device__ __forceinline__ uint32_t pack_hi(float a, float b) {
    __nv_bfloat162 v = __halves2bfloat162(__float2bfloat16_rn(a), __float2bfloat16_rn(b));
    return *(uint32_t*)&v;
}
__device__ __forceinline__ uint32_t pack_lo(float a, float b) {
    __nv_bfloat16 ha = __float2bfloat16_rn(a), hb = __float2bfloat16_rn(b);
    __nv_bfloat162 v = __halves2bfloat162(
        __float2bfloat16_rn(a - __bfloat162float(ha)),
        __float2bfloat16_rn(b - __bfloat162float(hb)));
    return *(uint32_t*)&v;
}

// ---------------------------------------------------------------------------
// RoPE table (validated R4/R6)
// ---------------------------------------------------------------------------
__global__ void rope_tab_k() {
    int i = blockIdx.x * 256 + threadIdx.x;
    if (i >= NT * 60) return;
    int n = i / 60;
    int d = i - n * 60;
    int axis = d / 20;
    int fi = (d % 20) % 10;
    int fr = n / 196;
    int inf = n - fr * 196;
    int hh = inf / 14;
    int ww = inf - hh * 14;
    float pos = (axis == 0) ? (float)fr : ((axis == 1) ? (float)hh : (float)ww);
    float omega = 1.0f / powf(10000.0f, (float)fi * 0.1f);
    g_ctab[i] = cosf(pos * omega);
    g_stab[i] = sinf(pos * omega);
}

// ---------------------------------------------------------------------------
// fp32 -> (bf16 hi, bf16 lo).  which: 0=x, 1=Wqkv, 2=Wproj
// ---------------------------------------------------------------------------
__global__ void split_k(const float* __restrict__ s, int which, int n4) {
    int i = blockIdx.x * 256 + threadIdx.x;
    if (i >= n4) return;
    __nv_bfloat16 *h, *l;
    if (which == 0)      { h = g_xh;  l = g_xl;  }
    else if (which == 1) { h = g_wqh; l = g_wql; }
    else                 { h = g_wph; l = g_wpl; }
    float4 v = ((const float4*)s)[i];
    ((uint32_t*)h)[2 * i]     = pack_hi(v.x, v.y);
    ((uint32_t*)h)[2 * i + 1] = pack_hi(v.z, v.w);
    ((uint32_t*)l)[2 * i]     = pack_lo(v.x, v.y);
    ((uint32_t*)l)[2 * i + 1] = pack_lo(v.z, v.w);
}

// ---------------------------------------------------------------------------
// mma.sync bf16 split GEMM with cp.async double buffering.
// C = A * B^T (K-major, K=1024). Tile 128x128, BK=32, 8 warps (4m x 2n).
// EPI 0: QKV + RoPE -> bf16 hi/lo q/k/v (q pre-scaled 1/8). grid 24x49
// EPI 1: out-projection + bias -> Cout.                     grid  8x49
// ---------------------------------------------------------------------------
#define TILE_B 10240                 // one operand tile: 128 rows * 80 B
#define STG_B (4 * TILE_B)           // one stage: AH AL BH BL = 40960 B
#define OFF_AH 0
#define OFF_AL (TILE_B)
#define OFF_BH (2 * TILE_B)
#define OFF_BL (3 * TILE_B)
#define GEMM_SMEM (2 * STG_B)        // 81920 B

template <int EPI>
__global__ __launch_bounds__(256, 2) void gemm_mma(
    float* __restrict__ Cout, const float* __restrict__ bias)
{
    extern __shared__ __align__(16) char sm[];
    const uint32_t sb = smem_u32(sm);

    const int tid = threadIdx.x;
    const int lane = tid & 31;
    const int wid = tid >> 5;
    const int wm = wid & 3;
    const int wn = wid >> 2;
    const int bx = blockIdx.x;
    const int by = blockIdx.y;

    const __nv_bfloat16* Agh = (EPI == 0) ? g_xh  : g_oh;
    const __nv_bfloat16* Agl = (EPI == 0) ? g_xl  : g_ol;
    const __nv_bfloat16* Bgh = (EPI == 0) ? g_wqh : g_wph;
    const __nv_bfloat16* Bgl = (EPI == 0) ? g_wql : g_wpl;

    float acc[2][8][4];
#pragma unroll
    for (int mi = 0; mi < 2; mi++)
#pragma unroll
        for (int ni = 0; ni < 8; ni++)
#pragma unroll
            for (int j = 0; j < 4; j++) acc[mi][ni][j] = 0.0f;

    const int lrow = tid >> 2;
    const int lch = tid & 3;
    const uint32_t a_off = (uint32_t)(((wm * 32 + (lane & 15)) * 40 + ((lane >> 4) << 3)) * 2);
    const uint32_t b_off = (uint32_t)(((wn * 64 + (lane & 7) + ((lane >> 4) << 3)) * 40 +
                                      (((lane >> 3) & 1) << 3)) * 2);

    auto issue_tile = [&](int s, int buf) {
        const int k0 = s * 32;
        const uint32_t bbs = sb + buf * STG_B;
#pragma unroll
        for (int hh = 0; hh < 2; hh++) {
            int r = lrow + hh * 64;
            size_t ga = (size_t)(by * 128 + r) * 1024 + k0 + lch * 8;
            size_t gb = (size_t)(bx * 128 + r) * 1024 + k0 + lch * 8;
            uint32_t so = bbs + (uint32_t)((r * 40 + lch * 8) * 2);
            cp16(so + OFF_AH, Agh + ga);
            cp16(so + OFF_AL, Agl + ga);
            cp16(so + OFF_BH, Bgh + gb);
            cp16(so + OFF_BL, Bgl + gb);
        }
    };

    issue_tile(0, 0);
    CP_COMMIT();

#pragma unroll 1
    for (int s = 0; s < 32; s++) {
        if (s + 1 < 32) {
            issue_tile(s + 1, (s + 1) & 1);
            CP_COMMIT();
            CP_WAIT(1);
        } else {
            CP_WAIT(0);
        }
        __syncthreads();

        const uint32_t bbs = sb + (s & 1) * STG_B;
#pragma unroll
        for (int ks = 0; ks < 2; ks++) {
            const uint32_t kb = (uint32_t)(ks * 32);
            uint32_t ah[2][4], al[2][4];
            ldm4(ah[0], bbs + OFF_AH + a_off + kb);
            ldm4(ah[1], bbs + OFF_AH + a_off + kb + 16 * 80);
            ldm4(al[0], bbs + OFF_AL + a_off + kb);
            ldm4(al[1], bbs + OFF_AL + a_off + kb + 16 * 80);
#pragma unroll
            for (int np = 0; np < 4; np++) {
                uint32_t bh[4], bl[4];
                ldm4(bh, bbs + OFF_BH + b_off + kb + np * 16 * 80);
                ldm4(bl, bbs + OFF_BL + b_off + kb + np * 16 * 80);
#pragma unroll
                for (int mi = 0; mi < 2; mi++) {
                    mma16816(acc[mi][2 * np],     ah[mi], bh);
                    mma16816(acc[mi][2 * np + 1], ah[mi], bh + 2);
                    mma16816(acc[mi][2 * np],     ah[mi], bl);
                    mma16816(acc[mi][2 * np + 1], ah[mi], bl + 2);
                    mma16816(acc[mi][2 * np],     al[mi], bh);
                    mma16816(acc[mi][2 * np + 1], al[mi], bh + 2);
                }
            }
        }
        __syncthreads();
    }

    const int g = lane >> 2;
    const int t = lane & 3;
#pragma unroll
    for (int mi = 0; mi < 2; mi++) {
#pragma unroll
        for (int ni = 0; ni < 8; ni++) {
#pragma unroll
            for (int half = 0; half < 2; half++) {
                int rr = wm * 32 + mi * 16 + g + half * 8;
                int o = bx * 128 + wn * 64 + ni * 8 + 2 * t;
                float e = acc[mi][ni][2 * half];
                float oo = acc[mi][ni][2 * half + 1];
                int m = by * 128 + rr;
                if (EPI == 0) {
                    int b = m / NT;
                    int n = m - b * NT;
                    int nb = n * 60;
                    int sidx = o >> 10;
                    int hd = (o & 1023) >> 6;
                    int d = o & 63;
                    float oe = e, of = oo;
                    if (sidx < 2 && d < 60) {
                        float c0 = g_ctab[nb + d],     s0 = g_stab[nb + d];
                        float c1 = g_ctab[nb + d + 1], s1 = g_stab[nb + d + 1];
                        oe = fmaf(e, c0, -oo * s0);
                        of = fmaf(oo, c1, e * s1);
                    }
                    if (sidx == 0) { oe *= 0.125f; of *= 0.125f; }
                    __nv_bfloat16 *dh, *dl;
                    if (sidx == 0)      { dh = g_qh; dl = g_ql; }
                    else if (sidx == 1) { dh = g_kh; dl = g_kl; }
                    else                { dh = g_vh; dl = g_vl; }
                    size_t base = ((size_t)((b * NH + hd) * NT + n)) * 64 + d;
                    *(uint32_t*)&dh[base] = pack_hi(oe, of);
                    *(uint32_t*)&dl[base] = pack_lo(oe, of);
                } else {
                    float2 bv = *(const float2*)&bias[o];
                    *(float2*)&Cout[(size_t)m * CC + o] = make_float2(e + bv.x, oo + bv.y);
                }
            }
        }
    }
}

// ---------------------------------------------------------------------------
// Tensor-core flash attention with cp.async double-buffered K/V.
// grid (13 q-tiles, 64 bh). BQ=128, BK=64, 8 warps x m16 rows.
// Byte layout: QH 0, QL 18432; KV stage s at 36864 + s*36864 with
//   KH +0, KL +9216, VH +18432, VL +27648 (row stride 144 B).
// ---------------------------------------------------------------------------
#define AST 72
#define QH_B 0
#define QL_B (128 * AST * 2)
#define KV0_B (2 * 128 * AST * 2)
#define KVSTG_B (4 * 64 * AST * 2)       // 36864
#define KL_B (64 * AST * 2)
#define VH_B (2 * 64 * AST * 2)
#define VL_B (3 * 64 * AST * 2)
#define ATTN_SMEM (KV0_B + 2 * KVSTG_B)  // 110592 bytes

__global__ __launch_bounds__(256) void attn_k() {
    extern __shared__ __align__(16) __nv_bfloat16 smb[];
    const uint32_t sb = smem_u32(smb);

    const int tid = threadIdx.x;
    const int lane = tid & 31;
    const int wid = tid >> 5;
    const int g = lane >> 2;
    const int t = lane & 3;
    const int bh = blockIdx.y;
    const int bb = bh >> 4;
    const int hh = bh & 15;
    const int q0 = blockIdx.x * 128;

    const size_t hb = (size_t)(bb * NH + hh) * NT * 64;

    // Load Q tile (hi & lo)
#pragma unroll
    for (int i = 0; i < 4; i++) {
        int idx = i * 256 + tid;
        int r = idx >> 3, c = idx & 7;
        int gr = q0 + r;
        float4 vh = make_float4(0.f, 0.f, 0.f, 0.f), vl = vh;
        if (gr < NT) {
            vh = ((const float4*)(g_qh + hb + (size_t)gr * 64))[c];
            vl = ((const float4*)(g_ql + hb + (size_t)gr * 64))[c];
        }
        *(float4*)((char*)smb + QH_B + (r * AST + c * 8) * 2) = vh;
        *(float4*)((char*)smb + QL_B + (r * AST + c * 8) * 2) = vl;
    }

    auto issue_kv = [&](int kt, int buf) {
        const int k0 = kt * 64;
        const uint32_t bbs = sb + KV0_B + buf * KVSTG_B;
#pragma unroll
        for (int i = 0; i < 2; i++) {
            int idx = i * 256 + tid;
            int r = idx >> 3, c = idx & 7;
            int gr = k0 + r;
            int sz = (gr < NT) ? 16 : 0;
            int grc = (gr < NT) ? gr : (NT - 1);
            size_t go = hb + (size_t)grc * 64 + c * 8;
            uint32_t so = bbs + (uint32_t)((r * AST + c * 8) * 2);
            cp16z(so,        g_kh + go, sz);
            cp16z(so + KL_B, g_kl + go, sz);
            cp16z(so + VH_B, g_vh + go, sz);
            cp16z(so + VL_B, g_vl + go, sz);
        }
    };

    float oacc[8][4];
#pragma unroll
    for (int nd = 0; nd < 8; nd++)
#pragma unroll
        for (int j = 0; j < 4; j++) oacc[nd][j] = 0.f;
    float m2[2] = {-1e30f, -1e30f};
    float l2[2] = {0.f, 0.f};

    const uint32_t a_base = sb + QH_B + 2 * (uint32_t)((wid * 16 + (lane & 15)) * AST + ((lane >> 4) << 3));
    const uint32_t b_roff = (uint32_t)((lane & 7) + ((lane >> 4) << 3));
    const uint32_t b_coff = (uint32_t)(((lane >> 3) & 1) << 3);
    const uint32_t v_roff = (uint32_t)(lane & 15);
    const uint32_t v_coff = (uint32_t)((lane >> 4) << 3);

    issue_kv(0, 0);
    CP_COMMIT();

#pragma unroll 1
    for (int kt = 0; kt < 25; kt++) {
        const int k0 = kt * 64;
        if (kt + 1 < 25) {
            issue_kv(kt + 1, (kt + 1) & 1);
            CP_COMMIT();
            CP_WAIT(1);
        } else {
            CP_WAIT(0);
        }
        __syncthreads();
        const uint32_t kvb = sb + KV0_B + (kt & 1) * KVSTG_B;

        // S = Q K^T (3-way split)
        float sacc[8][4];
#pragma unroll
        for (int ni = 0; ni < 8; ni++)
#pragma unroll
            for (int j = 0; j < 4; j++) sacc[ni][j] = 0.f;

#pragma unroll
        for (int ds = 0; ds < 4; ds++) {
            uint32_t qh4[4], ql4[4];
            ldm4(qh4, a_base + 2 * (uint32_t)(ds * 16));
            ldm4(ql4, a_base + (QL_B - QH_B) + 2 * (uint32_t)(ds * 16));
#pragma unroll
            for (int ng = 0; ng < 4; ng++) {
                uint32_t kh4[4], kl4[4];
                uint32_t be = 2 * (uint32_t)((ng * 16 + b_roff) * AST + ds * 16 + b_coff);
                ldm4(kh4, kvb + be);
                ldm4(kl4, kvb + KL_B + be);
                mma16816(sacc[2 * ng],     qh4, kh4);
                mma16816(sacc[2 * ng + 1], qh4, kh4 + 2);
                mma16816(sacc[2 * ng],     qh4, kl4);
                mma16816(sacc[2 * ng + 1], qh4, kl4 + 2);
                mma16816(sacc[2 * ng],     ql4, kh4);
                mma16816(sacc[2 * ng + 1], ql4, kh4 + 2);
            }
        }

        // Online softmax
        if (k0 + 64 > NT) {
#pragma unroll
            for (int ni = 0; ni < 8; ni++) {
                int c0 = k0 + 8 * ni + 2 * t;
                if (c0 >= NT)     { sacc[ni][0] = -1e30f; sacc[ni][2] = -1e30f; }
                if (c0 + 1 >= NT) { sacc[ni][1] = -1e30f; sacc[ni][3] = -1e30f; }
            }
        }
#pragma unroll
        for (int h2 = 0; h2 < 2; h2++) {
            float mx = -1e30f;
#pragma unroll
            for (int ni = 0; ni < 8; ni++)
                mx = fmaxf(mx, fmaxf(sacc[ni][2 * h2], sacc[ni][2 * h2 + 1]));
            mx = fmaxf(mx, __shfl_xor_sync(0xffffffffu, mx, 1));
            mx = fmaxf(mx, __shfl_xor_sync(0xffffffffu, mx, 2));
            float mn = fmaxf(m2[h2], mx);
            float corr = __expf(m2[h2] - mn);
            m2[h2] = mn;
            float rs = 0.f;
#pragma unroll
            for (int ni = 0; ni < 8; ni++) {
                float p0 = __expf(sacc[ni][2 * h2] - mn);
                float p1 = __expf(sacc[ni][2 * h2 + 1] - mn);
                sacc[ni][2 * h2] = p0;
                sacc[ni][2 * h2 + 1] = p1;
                rs += p0 + p1;
            }
            rs += __shfl_xor_sync(0xffffffffu, rs, 1);
            rs += __shfl_xor_sync(0xffffffffu, rs, 2);
            l2[h2] = l2[h2] * corr + rs;
#pragma unroll
            for (int nd = 0; nd < 8; nd++) {
                oacc[nd][2 * h2] *= corr;
                oacc[nd][2 * h2 + 1] *= corr;
            }
        }

        // O += P V (3-way split)
#pragma unroll
        for (int kc = 0; kc < 4; kc++) {
            uint32_t ph[4], pl[4];
            ph[0] = pack_hi(sacc[2 * kc][0], sacc[2 * kc][1]);
            ph[1] = pack_hi(sacc[2 * kc][2], sacc[2 * kc][3]);
            ph[2] = pack_hi(sacc[2 * kc + 1][0], sacc[2 * kc + 1][1]);
            ph[3] = pack_hi(sacc[2 * kc + 1][2], sacc[2 * kc + 1][3]);
            pl[0] = pack_lo(sacc[2 * kc][0], sacc[2 * kc][1]);
            pl[1] = pack_lo(sacc[2 * kc][2], sacc[2 * kc][3]);
            pl[2] = pack_lo(sacc[2 * kc + 1][0], sacc[2 * kc + 1][1]);
            pl[3] = pack_lo(sacc[2 * kc + 1][2], sacc[2 * kc + 1][3]);
#pragma unroll
            for (int dg = 0; dg < 4; dg++) {
                uint32_t vh4[4], vl4[4];
                uint32_t ve = 2 * (uint32_t)((kc * 16 + v_roff) * AST + dg * 16 + v_coff);
                ldm4t(vh4, kvb + VH_B + ve);
                ldm4t(vl4, kvb + VL_B + ve);
                mma16816(oacc[2 * dg],     ph, vh4);
                mma16816(oacc[2 * dg + 1], ph, vh4 + 2);
                mma16816(oacc[2 * dg],     ph, vl4);
                mma16816(oacc[2 * dg + 1], ph, vl4 + 2);
                mma16816(oacc[2 * dg],     pl, vh4);
                mma16816(oacc[2 * dg + 1], pl, vh4 + 2);
            }
        }
        __syncthreads();
    }

    // Normalize, split to bf16 hi/lo, store to [B*N][C]
#pragma unroll
    for (int h2 = 0; h2 < 2; h2++) {
        int r = q0 + wid * 16 + g + 8 * h2;
        if (r < NT) {
            float inv = 1.0f / l2[h2];
            size_t ob = (size_t)(bb * NT + r) * CC + hh * 64;
#pragma unroll
            for (int nd = 0; nd < 8; nd++) {
                int col = 8 * nd + 2 * t;
                float o0 = oacc[nd][2 * h2] * inv;
                float o1 = oacc[nd][2 * h2 + 1] * inv;
                *(uint32_t*)&g_oh[ob + col] = pack_hi(o0, o1);
                *(uint32_t*)&g_ol[ob + col] = pack_lo(o0, o1);
            }
        }
    }
}

// ---------------------------------------------------------------------------
extern "C" void kernel_launch(void* const* d_in, const int* in_sizes, int n_in,
                              void* d_out, int out_size) {
    (void)in_sizes; (void)n_in; (void)out_size;
    const float* x = (const float*)d_in[0];
    const float* wqkv = (const float*)d_in[1];
    const float* wproj = (const float*)d_in[2];
    const float* bproj = (const float*)d_in[3];
    float* out = (float*)d_out;

    cudaFuncSetAttribute(attn_k, cudaFuncAttributeMaxDynamicSharedMemorySize, ATTN_SMEM);
    cudaFuncSetAttribute(gemm_mma<0>, cudaFuncAttributeMaxDynamicSharedMemorySize, GEMM_SMEM);
    cudaFuncSetAttribute(gemm_mma<1>, cudaFuncAttributeMaxDynamicSharedMemorySize, GEMM_SMEM);

    rope_tab_k<<<(NT * 60 + 255) / 256, 256>>>();

    int n4x = MROWS * CC / 4;
    int n4w = 3 * CC * CC / 4;
    int n4p = CC * CC / 4;
    split_k<<<(n4x + 255) / 256, 256>>>(x, 0, n4x);
    split_k<<<(n4w + 255) / 256, 256>>>(wqkv, 1, n4w);
    split_k<<<(n4p + 255) / 256, 256>>>(wproj, 2, n4p);

    gemm_mma<0><<<dim3(24, 49), 256, GEMM_SMEM>>>(nullptr, nullptr);
    attn_k<<<dim3(13, 64), 256, ATTN_SMEM>>>();
    gemm_mma<1><<<dim3(8, 49), 256, GEMM_SMEM>>>(out, bproj);
}

// round 9
// speedup vs baseline: 3.3796x; 1.3180x over previous
#include <cuda_runtime.h>
#include <cuda_bf16.h>
#include <cuda_fp16.h>
#include <cstdint>

// Problem constants
#define BB 4
#define NT 1568
#define NH 16
#define HD 64
#define CC 1024
#define MROWS (BB * NT)          // 6272

// ---------------------------------------------------------------------------
// Scratch (device globals — no allocations allowed)
// ---------------------------------------------------------------------------
static __device__ __align__(16) float g_ctab[NT * 60];
static __device__ __align__(16) float g_stab[NT * 60];
static __device__ __align__(16) __nv_bfloat16 g_xh[MROWS * CC],  g_xl[MROWS * CC];
static __device__ __align__(16) __nv_bfloat16 g_wqh[3 * CC * CC], g_wql[3 * CC * CC];
static __device__ __align__(16) __nv_bfloat16 g_wph[CC * CC],    g_wpl[CC * CC];
#define QKVN (BB * NH * NT * HD)
static __device__ __align__(16) __half g_qf[QKVN], g_kf[QKVN], g_vf[QKVN];
static __device__ __align__(16) __nv_bfloat16 g_oh[MROWS * CC], g_ol[MROWS * CC];

// ---------------------------------------------------------------------------
// Baseline-PTX helpers (plain sm_100 target)
// ---------------------------------------------------------------------------
__device__ __forceinline__ uint32_t smem_u32(const void* p) {
    uint32_t a;
    asm("{ .reg .u64 t; cvta.to.shared.u64 t, %1; cvt.u32.u64 %0, t; }" : "=r"(a) : "l"(p));
    return a;
}
__device__ __forceinline__ void ldm4(uint32_t* r, uint32_t addr) {
    asm volatile("ldmatrix.sync.aligned.m8n8.x4.shared.b16 {%0,%1,%2,%3}, [%4];"
                 : "=r"(r[0]), "=r"(r[1]), "=r"(r[2]), "=r"(r[3]) : "r"(addr));
}
__device__ __forceinline__ void ldm4t(uint32_t* r, uint32_t addr) {
    asm volatile("ldmatrix.sync.aligned.m8n8.x4.trans.shared.b16 {%0,%1,%2,%3}, [%4];"
                 : "=r"(r[0]), "=r"(r[1]), "=r"(r[2]), "=r"(r[3]) : "r"(addr));
}
__device__ __forceinline__ void mma16816(float* c, const uint32_t* a, const uint32_t* b) {
    asm volatile(
        "mma.sync.aligned.m16n8k16.row.col.f32.bf16.bf16.f32 "
        "{%0,%1,%2,%3}, {%4,%5,%6,%7}, {%8,%9}, {%0,%1,%2,%3};"
        : "+f"(c[0]), "+f"(c[1]), "+f"(c[2]), "+f"(c[3])
        : "r"(a[0]), "r"(a[1]), "r"(a[2]), "r"(a[3]), "r"(b[0]), "r"(b[1]));
}
__device__ __forceinline__ void mma16816h(float* c, const uint32_t* a, const uint32_t* b) {
    asm volatile(
        "mma.sync.aligned.m16n8k16.row.col.f32.f16.f16.f32 "
        "{%0,%1,%2,%3}, {%4,%5,%6,%7}, {%8,%9}, {%0,%1,%2,%3};"
        : "+f"(c[0]), "+f"(c[1]), "+f"(c[2]), "+f"(c[3])
        : "r"(a[0]), "r"(a[1]), "r"(a[2]), "r"(a[3]), "r"(b[0]), "r"(b[1]));
}
__device__ __forceinline__ void cp16(uint32_t s, const void* g) {
    asm volatile("cp.async.cg.shared.global [%0], [%1], 16;" :: "r"(s), "l"(g));
}
__device__ __forceinline__ void cp16z(uint32_t s, const void* g, int sz) {
    asm volatile("cp.async.cg.shared.global [%0], [%1], 16, %2;" :: "r"(s), "l"(g), "r"(sz));
}
#define CP_COMMIT() asm volatile("cp.async.commit_group;" ::: "memory")
#define CP_WAIT(n)  asm volatile("cp.async.wait_group %0;" :: "n"(n) : "memory")

__device__ __forceinline__ uint32_t pack_hi(float a, float b) {
    __nv_bfloat162 v = __halves2bfloat162(__float2bfloat16_rn(a), __float2bfloat16_rn(b));
    return *(uint32_t*)&v;
}
__device__ __forceinline__ uint32_t pack_lo(float a, float b) {
    __nv_bfloat16 ha = __float2bfloat16_rn(a), hb = __float2bfloat16_rn(b);
    __nv_bfloat162 v = __halves2bfloat162(
        __float2bfloat16_rn(a - __bfloat162float(ha)),
        __float2bfloat16_rn(b - __bfloat162float(hb)));
    return *(uint32_t*)&v;
}
__device__ __forceinline__ uint32_t pack_h2(float a, float b) {
    __half2 v = __floats2half2_rn(a, b);
    return *(uint32_t*)&v;
}

// ---------------------------------------------------------------------------
// RoPE table (validated R4/R6)
// ---------------------------------------------------------------------------
__global__ void rope_tab_k() {
    int i = blockIdx.x * 256 + threadIdx.x;
    if (i >= NT * 60) return;
    int n = i / 60;
    int d = i - n * 60;
    int axis = d / 20;
    int fi = (d % 20) % 10;
    int fr = n / 196;
    int inf = n - fr * 196;
    int hh = inf / 14;
    int ww = inf - hh * 14;
    float pos = (axis == 0) ? (float)fr : ((axis == 1) ? (float)hh : (float)ww);
    float omega = 1.0f / powf(10000.0f, (float)fi * 0.1f);
    g_ctab[i] = cosf(pos * omega);
    g_stab[i] = sinf(pos * omega);
}

// ---------------------------------------------------------------------------
// fp32 -> (bf16 hi, bf16 lo).  which: 0=x, 1=Wqkv, 2=Wproj
// ---------------------------------------------------------------------------
__global__ void split_k(const float* __restrict__ s, int which, int n4) {
    int i = blockIdx.x * 256 + threadIdx.x;
    if (i >= n4) return;
    __nv_bfloat16 *h, *l;
    if (which == 0)      { h = g_xh;  l = g_xl;  }
    else if (which == 1) { h = g_wqh; l = g_wql; }
    else                 { h = g_wph; l = g_wpl; }
    float4 v = ((const float4*)s)[i];
    ((uint32_t*)h)[2 * i]     = pack_hi(v.x, v.y);
    ((uint32_t*)h)[2 * i + 1] = pack_hi(v.z, v.w);
    ((uint32_t*)l)[2 * i]     = pack_lo(v.x, v.y);
    ((uint32_t*)l)[2 * i + 1] = pack_lo(v.z, v.w);
}

// ---------------------------------------------------------------------------
// mma.sync bf16 split GEMM with cp.async double buffering (validated R8).
// EPI 0: QKV + RoPE -> fp16 q/k/v (q pre-scaled 1/8). grid 24x49
// EPI 1: out-projection + bias -> Cout.               grid  8x49
// ---------------------------------------------------------------------------
#define TILE_B 10240
#define STG_B (4 * TILE_B)
#define OFF_AH 0
#define OFF_AL (TILE_B)
#define OFF_BH (2 * TILE_B)
#define OFF_BL (3 * TILE_B)
#define GEMM_SMEM (2 * STG_B)        // 81920 B

template <int EPI>
__global__ __launch_bounds__(256, 2) void gemm_mma(
    float* __restrict__ Cout, const float* __restrict__ bias)
{
    extern __shared__ __align__(16) char sm[];
    const uint32_t sb = smem_u32(sm);

    const int tid = threadIdx.x;
    const int lane = tid & 31;
    const int wid = tid >> 5;
    const int wm = wid & 3;
    const int wn = wid >> 2;
    const int bx = blockIdx.x;
    const int by = blockIdx.y;

    const __nv_bfloat16* Agh = (EPI == 0) ? g_xh  : g_oh;
    const __nv_bfloat16* Agl = (EPI == 0) ? g_xl  : g_ol;
    const __nv_bfloat16* Bgh = (EPI == 0) ? g_wqh : g_wph;
    const __nv_bfloat16* Bgl = (EPI == 0) ? g_wql : g_wpl;

    float acc[2][8][4];
#pragma unroll
    for (int mi = 0; mi < 2; mi++)
#pragma unroll
        for (int ni = 0; ni < 8; ni++)
#pragma unroll
            for (int j = 0; j < 4; j++) acc[mi][ni][j] = 0.0f;

    const int lrow = tid >> 2;
    const int lch = tid & 3;
    const uint32_t a_off = (uint32_t)(((wm * 32 + (lane & 15)) * 40 + ((lane >> 4) << 3)) * 2);
    const uint32_t b_off = (uint32_t)(((wn * 64 + (lane & 7) + ((lane >> 4) << 3)) * 40 +
                                      (((lane >> 3) & 1) << 3)) * 2);

    auto issue_tile = [&](int s, int buf) {
        const int k0 = s * 32;
        const uint32_t bbs = sb + buf * STG_B;
#pragma unroll
        for (int hh = 0; hh < 2; hh++) {
            int r = lrow + hh * 64;
            size_t ga = (size_t)(by * 128 + r) * 1024 + k0 + lch * 8;
            size_t gb = (size_t)(bx * 128 + r) * 1024 + k0 + lch * 8;
            uint32_t so = bbs + (uint32_t)((r * 40 + lch * 8) * 2);
            cp16(so + OFF_AH, Agh + ga);
            cp16(so + OFF_AL, Agl + ga);
            cp16(so + OFF_BH, Bgh + gb);
            cp16(so + OFF_BL, Bgl + gb);
        }
    };

    issue_tile(0, 0);
    CP_COMMIT();

#pragma unroll 1
    for (int s = 0; s < 32; s++) {
        if (s + 1 < 32) {
            issue_tile(s + 1, (s + 1) & 1);
            CP_COMMIT();
            CP_WAIT(1);
        } else {
            CP_WAIT(0);
        }
        __syncthreads();

        const uint32_t bbs = sb + (s & 1) * STG_B;
#pragma unroll
        for (int ks = 0; ks < 2; ks++) {
            const uint32_t kb = (uint32_t)(ks * 32);
            uint32_t ah[2][4], al[2][4];
            ldm4(ah[0], bbs + OFF_AH + a_off + kb);
            ldm4(ah[1], bbs + OFF_AH + a_off + kb + 16 * 80);
            ldm4(al[0], bbs + OFF_AL + a_off + kb);
            ldm4(al[1], bbs + OFF_AL + a_off + kb + 16 * 80);
#pragma unroll
            for (int np = 0; np < 4; np++) {
                uint32_t bh[4], bl[4];
                ldm4(bh, bbs + OFF_BH + b_off + kb + np * 16 * 80);
                ldm4(bl, bbs + OFF_BL + b_off + kb + np * 16 * 80);
#pragma unroll
                for (int mi = 0; mi < 2; mi++) {
                    mma16816(acc[mi][2 * np],     ah[mi], bh);
                    mma16816(acc[mi][2 * np + 1], ah[mi], bh + 2);
                    mma16816(acc[mi][2 * np],     ah[mi], bl);
                    mma16816(acc[mi][2 * np + 1], ah[mi], bl + 2);
                    mma16816(acc[mi][2 * np],     al[mi], bh);
                    mma16816(acc[mi][2 * np + 1], al[mi], bh + 2);
                }
            }
        }
        __syncthreads();
    }

    const int g = lane >> 2;
    const int t = lane & 3;
#pragma unroll
    for (int mi = 0; mi < 2; mi++) {
#pragma unroll
        for (int ni = 0; ni < 8; ni++) {
#pragma unroll
            for (int half = 0; half < 2; half++) {
                int rr = wm * 32 + mi * 16 + g + half * 8;
                int o = bx * 128 + wn * 64 + ni * 8 + 2 * t;
                float e = acc[mi][ni][2 * half];
                float oo = acc[mi][ni][2 * half + 1];
                int m = by * 128 + rr;
                if (EPI == 0) {
                    int b = m / NT;
                    int n = m - b * NT;
                    int nb = n * 60;
                    int sidx = o >> 10;
                    int hd = (o & 1023) >> 6;
                    int d = o & 63;
                    float oe = e, of = oo;
                    if (sidx < 2 && d < 60) {
                        float c0 = g_ctab[nb + d],     s0 = g_stab[nb + d];
                        float c1 = g_ctab[nb + d + 1], s1 = g_stab[nb + d + 1];
                        oe = fmaf(e, c0, -oo * s0);
                        of = fmaf(oo, c1, e * s1);
                    }
                    if (sidx == 0) { oe *= 0.125f; of *= 0.125f; }
                    __half* df = (sidx == 0) ? g_qf : ((sidx == 1) ? g_kf : g_vf);
                    size_t base = ((size_t)((b * NH + hd) * NT + n)) * 64 + d;
                    *(uint32_t*)&df[base] = pack_h2(oe, of);
                } else {
                    float2 bv = *(const float2*)&bias[o];
                    *(float2*)&Cout[(size_t)m * CC + o] = make_float2(e + bv.x, oo + bv.y);
                }
            }
        }
    }
}

// ---------------------------------------------------------------------------
// fp16 tensor-core flash attention, cp.async double-buffered K/V.
// grid (13 q-tiles, 64 bh). BQ=128, BK=64, 8 warps x m16 rows.
// Byte layout: QF 0 (18432); KV stage s at 18432 + s*18432: K +0, V +9216.
// ---------------------------------------------------------------------------
#define AST 72
#define QF_B 0
#define KV0_B (128 * AST * 2)            // 18432
#define KVSTG_B (2 * 64 * AST * 2)       // 18432
#define V_B (64 * AST * 2)               // 9216
#define ATTN_SMEM (KV0_B + 2 * KVSTG_B)  // 55296 bytes

__global__ __launch_bounds__(256) void attn_k() {
    extern __shared__ __align__(16) __half smh[];
    const uint32_t sb = smem_u32(smh);

    const int tid = threadIdx.x;
    const int lane = tid & 31;
    const int wid = tid >> 5;
    const int g = lane >> 2;
    const int t = lane & 3;
    const int bh = blockIdx.y;
    const int bb = bh >> 4;
    const int hh = bh & 15;
    const int q0 = blockIdx.x * 128;

    const size_t hb = (size_t)(bb * NH + hh) * NT * 64;

    // Load Q tile: 128x64 fp16 = 1024 16B-chunks
#pragma unroll
    for (int i = 0; i < 4; i++) {
        int idx = i * 256 + tid;
        int r = idx >> 3, c = idx & 7;
        int gr = q0 + r;
        float4 v = make_float4(0.f, 0.f, 0.f, 0.f);
        if (gr < NT) v = ((const float4*)(g_qf + hb + (size_t)gr * 64))[c];
        *(float4*)((char*)smh + QF_B + (r * AST + c * 8) * 2) = v;
    }

    auto issue_kv = [&](int kt, int buf) {
        const int k0 = kt * 64;
        const uint32_t bbs = sb + KV0_B + buf * KVSTG_B;
#pragma unroll
        for (int i = 0; i < 2; i++) {
            int idx = i * 256 + tid;
            int r = idx >> 3, c = idx & 7;
            int gr = k0 + r;
            int sz = (gr < NT) ? 16 : 0;
            int grc = (gr < NT) ? gr : (NT - 1);
            size_t go = hb + (size_t)grc * 64 + c * 8;
            uint32_t so = bbs + (uint32_t)((r * AST + c * 8) * 2);
            cp16z(so,       g_kf + go, sz);
            cp16z(so + V_B, g_vf + go, sz);
        }
    };

    float oacc[8][4];
#pragma unroll
    for (int nd = 0; nd < 8; nd++)
#pragma unroll
        for (int j = 0; j < 4; j++) oacc[nd][j] = 0.f;
    float m2[2] = {-1e30f, -1e30f};
    float l2[2] = {0.f, 0.f};

    const uint32_t a_base = sb + QF_B + 2 * (uint32_t)((wid * 16 + (lane & 15)) * AST + ((lane >> 4) << 3));
    const uint32_t b_roff = (uint32_t)((lane & 7) + ((lane >> 4) << 3));
    const uint32_t b_coff = (uint32_t)(((lane >> 3) & 1) << 3);
    const uint32_t v_roff = (uint32_t)(lane & 15);
    const uint32_t v_coff = (uint32_t)((lane >> 4) << 3);

    issue_kv(0, 0);
    CP_COMMIT();

#pragma unroll 1
    for (int kt = 0; kt < 25; kt++) {
        const int k0 = kt * 64;
        if (kt + 1 < 25) {
            issue_kv(kt + 1, (kt + 1) & 1);
            CP_COMMIT();
            CP_WAIT(1);
        } else {
            CP_WAIT(0);
        }
        __syncthreads();
        const uint32_t kvb = sb + KV0_B + (kt & 1) * KVSTG_B;

        // S = Q K^T (fp16 single)
        float sacc[8][4];
#pragma unroll
        for (int ni = 0; ni < 8; ni++)
#pragma unroll
            for (int j = 0; j < 4; j++) sacc[ni][j] = 0.f;

#pragma unroll
        for (int ds = 0; ds < 4; ds++) {
            uint32_t q4[4];
            ldm4(q4, a_base + 2 * (uint32_t)(ds * 16));
#pragma unroll
            for (int ng = 0; ng < 4; ng++) {
                uint32_t k4[4];
                uint32_t be = 2 * (uint32_t)((ng * 16 + b_roff) * AST + ds * 16 + b_coff);
                ldm4(k4, kvb + be);
                mma16816h(sacc[2 * ng],     q4, k4);
                mma16816h(sacc[2 * ng + 1], q4, k4 + 2);
            }
        }

        // Online softmax
        if (k0 + 64 > NT) {
#pragma unroll
            for (int ni = 0; ni < 8; ni++) {
                int c0 = k0 + 8 * ni + 2 * t;
                if (c0 >= NT)     { sacc[ni][0] = -1e30f; sacc[ni][2] = -1e30f; }
                if (c0 + 1 >= NT) { sacc[ni][1] = -1e30f; sacc[ni][3] = -1e30f; }
            }
        }
#pragma unroll
        for (int h2 = 0; h2 < 2; h2++) {
            float mx = -1e30f;
#pragma unroll
            for (int ni = 0; ni < 8; ni++)
                mx = fmaxf(mx, fmaxf(sacc[ni][2 * h2], sacc[ni][2 * h2 + 1]));
            mx = fmaxf(mx, __shfl_xor_sync(0xffffffffu, mx, 1));
            mx = fmaxf(mx, __shfl_xor_sync(0xffffffffu, mx, 2));
            float mn = fmaxf(m2[h2], mx);
            float corr = __expf(m2[h2] - mn);
            m2[h2] = mn;
            float rs = 0.f;
#pragma unroll
            for (int ni = 0; ni < 8; ni++) {
                float p0 = __expf(sacc[ni][2 * h2] - mn);
                float p1 = __expf(sacc[ni][2 * h2 + 1] - mn);
                sacc[ni][2 * h2] = p0;
                sacc[ni][2 * h2 + 1] = p1;
                rs += p0 + p1;
            }
            rs += __shfl_xor_sync(0xffffffffu, rs, 1);
            rs += __shfl_xor_sync(0xffffffffu, rs, 2);
            l2[h2] = l2[h2] * corr + rs;
#pragma unroll
            for (int nd = 0; nd < 8; nd++) {
                oacc[nd][2 * h2] *= corr;
                oacc[nd][2 * h2 + 1] *= corr;
            }
        }

        // O += P V (fp16 single)
#pragma unroll
        for (int kc = 0; kc < 4; kc++) {
            uint32_t ph[4];
            ph[0] = pack_h2(sacc[2 * kc][0], sacc[2 * kc][1]);
            ph[1] = pack_h2(sacc[2 * kc][2], sacc[2 * kc][3]);
            ph[2] = pack_h2(sacc[2 * kc + 1][0], sacc[2 * kc + 1][1]);
            ph[3] = pack_h2(sacc[2 * kc + 1][2], sacc[2 * kc + 1][3]);
#pragma unroll
            for (int dg = 0; dg < 4; dg++) {
                uint32_t v4[4];
                uint32_t ve = 2 * (uint32_t)((kc * 16 + v_roff) * AST + dg * 16 + v_coff);
                ldm4t(v4, kvb + V_B + ve);
                mma16816h(oacc[2 * dg],     ph, v4);
                mma16816h(oacc[2 * dg + 1], ph, v4 + 2);
            }
        }
        __syncthreads();
    }

    // Normalize, split to bf16 hi/lo, store to [B*N][C]
#pragma unroll
    for (int h2 = 0; h2 < 2; h2++) {
        int r = q0 + wid * 16 + g + 8 * h2;
        if (r < NT) {
            float inv = 1.0f / l2[h2];
            size_t ob = (size_t)(bb * NT + r) * CC + hh * 64;
#pragma unroll
            for (int nd = 0; nd < 8; nd++) {
                int col = 8 * nd + 2 * t;
                float o0 = oacc[nd][2 * h2] * inv;
                float o1 = oacc[nd][2 * h2 + 1] * inv;
                *(uint32_t*)&g_oh[ob + col] = pack_hi(o0, o1);
                *(uint32_t*)&g_ol[ob + col] = pack_lo(o0, o1);
            }
        }
    }
}

// ---------------------------------------------------------------------------
extern "C" void kernel_launch(void* const* d_in, const int* in_sizes, int n_in,
                              void* d_out, int out_size) {
    (void)in_sizes; (void)n_in; (void)out_size;
    const float* x = (const float*)d_in[0];
    const float* wqkv = (const float*)d_in[1];
    const float* wproj = (const float*)d_in[2];
    const float* bproj = (const float*)d_in[3];
    float* out = (float*)d_out;

    cudaFuncSetAttribute(attn_k, cudaFuncAttributeMaxDynamicSharedMemorySize, ATTN_SMEM);
    cudaFuncSetAttribute(gemm_mma<0>, cudaFuncAttributeMaxDynamicSharedMemorySize, GEMM_SMEM);
    cudaFuncSetAttribute(gemm_mma<1>, cudaFuncAttributeMaxDynamicSharedMemorySize, GEMM_SMEM);

    rope_tab_k<<<(NT * 60 + 255) / 256, 256>>>();

    int n4x = MROWS * CC / 4;
    int n4w = 3 * CC * CC / 4;
    int n4p = CC * CC / 4;
    split_k<<<(n4x + 255) / 256, 256>>>(x, 0, n4x);
    split_k<<<(n4w + 255) / 256, 256>>>(wqkv, 1, n4w);
    split_k<<<(n4p + 255) / 256, 256>>>(wproj, 2, n4p);

    gemm_mma<0><<<dim3(24, 49), 256, GEMM_SMEM>>>(nullptr, nullptr);
    attn_k<<<dim3(13, 64), 256, ATTN_SMEM>>>();
    gemm_mma<1><<<dim3(8, 49), 256, GEMM_SMEM>>>(out, bproj);
}

// round 10
// speedup vs baseline: 5.5243x; 1.6346x over previous
#include <cuda_runtime.h>
#include <cuda_bf16.h>
#include <cuda_fp16.h>
#include <cstdint>

// Problem constants
#define BB 4
#define NT 1568
#define NH 16
#define HD 64
#define CC 1024
#define MROWS (BB * NT)          // 6272

// ---------------------------------------------------------------------------
// Scratch (device globals — no allocations allowed)
// ---------------------------------------------------------------------------
static __device__ __align__(16) float g_ctab[NT * 60];
static __device__ __align__(16) float g_stab[NT * 60];
static __device__ __align__(16) __half g_xf[MROWS * CC];
static __device__ __align__(16) __half g_wqf[3 * CC * CC];
static __device__ __align__(16) __half g_wpf[CC * CC];
#define QKVN (BB * NH * NT * HD)
static __device__ __align__(16) __half g_qf[QKVN], g_kf[QKVN], g_vf[QKVN];
static __device__ __align__(16) __half g_of[MROWS * CC];

// ---------------------------------------------------------------------------
// Baseline-PTX helpers (plain sm_100 target)
// ---------------------------------------------------------------------------
__device__ __forceinline__ uint32_t smem_u32(const void* p) {
    uint32_t a;
    asm("{ .reg .u64 t; cvta.to.shared.u64 t, %1; cvt.u32.u64 %0, t; }" : "=r"(a) : "l"(p));
    return a;
}
__device__ __forceinline__ void ldm4(uint32_t* r, uint32_t addr) {
    asm volatile("ldmatrix.sync.aligned.m8n8.x4.shared.b16 {%0,%1,%2,%3}, [%4];"
                 : "=r"(r[0]), "=r"(r[1]), "=r"(r[2]), "=r"(r[3]) : "r"(addr));
}
__device__ __forceinline__ void ldm4t(uint32_t* r, uint32_t addr) {
    asm volatile("ldmatrix.sync.aligned.m8n8.x4.trans.shared.b16 {%0,%1,%2,%3}, [%4];"
                 : "=r"(r[0]), "=r"(r[1]), "=r"(r[2]), "=r"(r[3]) : "r"(addr));
}
__device__ __forceinline__ void mma16816h(float* c, const uint32_t* a, const uint32_t* b) {
    asm volatile(
        "mma.sync.aligned.m16n8k16.row.col.f32.f16.f16.f32 "
        "{%0,%1,%2,%3}, {%4,%5,%6,%7}, {%8,%9}, {%0,%1,%2,%3};"
        : "+f"(c[0]), "+f"(c[1]), "+f"(c[2]), "+f"(c[3])
        : "r"(a[0]), "r"(a[1]), "r"(a[2]), "r"(a[3]), "r"(b[0]), "r"(b[1]));
}
__device__ __forceinline__ void cp16(uint32_t s, const void* g) {
    asm volatile("cp.async.cg.shared.global [%0], [%1], 16;" :: "r"(s), "l"(g));
}
__device__ __forceinline__ void cp16z(uint32_t s, const void* g, int sz) {
    asm volatile("cp.async.cg.shared.global [%0], [%1], 16, %2;" :: "r"(s), "l"(g), "r"(sz));
}
#define CP_COMMIT() asm volatile("cp.async.commit_group;" ::: "memory")
#define CP_WAIT(n)  asm volatile("cp.async.wait_group %0;" :: "n"(n) : "memory")

__device__ __forceinline__ uint32_t pack_h2(float a, float b) {
    __half2 v = __floats2half2_rn(a, b);
    return *(uint32_t*)&v;
}

// ---------------------------------------------------------------------------
// RoPE table (validated R4/R6)
// ---------------------------------------------------------------------------
__global__ void rope_tab_k() {
    int i = blockIdx.x * 256 + threadIdx.x;
    if (i >= NT * 60) return;
    int n = i / 60;
    int d = i - n * 60;
    int axis = d / 20;
    int fi = (d % 20) % 10;
    int fr = n / 196;
    int inf = n - fr * 196;
    int hh = inf / 14;
    int ww = inf - hh * 14;
    float pos = (axis == 0) ? (float)fr : ((axis == 1) ? (float)hh : (float)ww);
    float omega = 1.0f / powf(10000.0f, (float)fi * 0.1f);
    g_ctab[i] = cosf(pos * omega);
    g_stab[i] = sinf(pos * omega);
}

// ---------------------------------------------------------------------------
// fp32 -> fp16.  which: 0=x, 1=Wqkv, 2=Wproj
// ---------------------------------------------------------------------------
__global__ void conv_k(const float* __restrict__ s, int which, int n4) {
    int i = blockIdx.x * 256 + threadIdx.x;
    if (i >= n4) return;
    __half* d = (which == 0) ? g_xf : ((which == 1) ? g_wqf : g_wpf);
    float4 v = ((const float4*)s)[i];
    ((uint32_t*)d)[2 * i]     = pack_h2(v.x, v.y);
    ((uint32_t*)d)[2 * i + 1] = pack_h2(v.z, v.w);
}

// ---------------------------------------------------------------------------
// mma.sync fp16 GEMM with cp.async double buffering.
// C = A * B^T (K-major, K=1024). Tile 128x128, BK=32, 8 warps (4m x 2n).
// EPI 0: QKV + RoPE -> fp16 q/k/v (q pre-scaled 1/8). grid 24x49
// EPI 1: out-projection + bias -> Cout.               grid  8x49
// Smem row stride 40 halves (80 B) -> conflict-free ldmatrix (validated R6-R9).
// ---------------------------------------------------------------------------
#define TILE_B 10240                 // 128 rows * 80 B
#define STG_B (2 * TILE_B)           // A + B per stage = 20480 B
#define OFF_A 0
#define OFF_B (TILE_B)
#define GEMM_SMEM (2 * STG_B)        // 40960 B

template <int EPI>
__global__ __launch_bounds__(256, 2) void gemm_mma(
    float* __restrict__ Cout, const float* __restrict__ bias)
{
    extern __shared__ __align__(16) char sm[];
    const uint32_t sb = smem_u32(sm);

    const int tid = threadIdx.x;
    const int lane = tid & 31;
    const int wid = tid >> 5;
    const int wm = wid & 3;
    const int wn = wid >> 2;
    const int bx = blockIdx.x;
    const int by = blockIdx.y;

    const __half* Ag = (EPI == 0) ? g_xf : g_of;
    const __half* Bg = (EPI == 0) ? g_wqf : g_wpf;

    float acc[2][8][4];
#pragma unroll
    for (int mi = 0; mi < 2; mi++)
#pragma unroll
        for (int ni = 0; ni < 8; ni++)
#pragma unroll
            for (int j = 0; j < 4; j++) acc[mi][ni][j] = 0.0f;

    const int lrow = tid >> 2;
    const int lch = tid & 3;
    const uint32_t a_off = (uint32_t)(((wm * 32 + (lane & 15)) * 40 + ((lane >> 4) << 3)) * 2);
    const uint32_t b_off = (uint32_t)(((wn * 64 + (lane & 7) + ((lane >> 4) << 3)) * 40 +
                                      (((lane >> 3) & 1) << 3)) * 2);

    auto issue_tile = [&](int s, int buf) {
        const int k0 = s * 32;
        const uint32_t bbs = sb + buf * STG_B;
#pragma unroll
        for (int hh = 0; hh < 2; hh++) {
            int r = lrow + hh * 64;
            size_t ga = (size_t)(by * 128 + r) * 1024 + k0 + lch * 8;
            size_t gb = (size_t)(bx * 128 + r) * 1024 + k0 + lch * 8;
            uint32_t so = bbs + (uint32_t)((r * 40 + lch * 8) * 2);
            cp16(so + OFF_A, Ag + ga);
            cp16(so + OFF_B, Bg + gb);
        }
    };

    issue_tile(0, 0);
    CP_COMMIT();

#pragma unroll 1
    for (int s = 0; s < 32; s++) {
        if (s + 1 < 32) {
            issue_tile(s + 1, (s + 1) & 1);
            CP_COMMIT();
            CP_WAIT(1);
        } else {
            CP_WAIT(0);
        }
        __syncthreads();

        const uint32_t bbs = sb + (s & 1) * STG_B;
#pragma unroll
        for (int ks = 0; ks < 2; ks++) {
            const uint32_t kb = (uint32_t)(ks * 32);
            uint32_t af[2][4];
            ldm4(af[0], bbs + OFF_A + a_off + kb);
            ldm4(af[1], bbs + OFF_A + a_off + kb + 16 * 80);
#pragma unroll
            for (int np = 0; np < 4; np++) {
                uint32_t bf[4];
                ldm4(bf, bbs + OFF_B + b_off + kb + np * 16 * 80);
#pragma unroll
                for (int mi = 0; mi < 2; mi++) {
                    mma16816h(acc[mi][2 * np],     af[mi], bf);
                    mma16816h(acc[mi][2 * np + 1], af[mi], bf + 2);
                }
            }
        }
        __syncthreads();
    }

    const int g = lane >> 2;
    const int t = lane & 3;
#pragma unroll
    for (int mi = 0; mi < 2; mi++) {
#pragma unroll
        for (int ni = 0; ni < 8; ni++) {
#pragma unroll
            for (int half = 0; half < 2; half++) {
                int rr = wm * 32 + mi * 16 + g + half * 8;
                int o = bx * 128 + wn * 64 + ni * 8 + 2 * t;
                float e = acc[mi][ni][2 * half];
                float oo = acc[mi][ni][2 * half + 1];
                int m = by * 128 + rr;
                if (EPI == 0) {
                    int b = m / NT;
                    int n = m - b * NT;
                    int nb = n * 60;
                    int sidx = o >> 10;
                    int hd = (o & 1023) >> 6;
                    int d = o & 63;
                    float oe = e, of = oo;
                    if (sidx < 2 && d < 60) {
                        float c0 = g_ctab[nb + d],     s0 = g_stab[nb + d];
                        float c1 = g_ctab[nb + d + 1], s1 = g_stab[nb + d + 1];
                        oe = fmaf(e, c0, -oo * s0);
                        of = fmaf(oo, c1, e * s1);
                    }
                    if (sidx == 0) { oe *= 0.125f; of *= 0.125f; }
                    __half* df = (sidx == 0) ? g_qf : ((sidx == 1) ? g_kf : g_vf);
                    size_t base = ((size_t)((b * NH + hd) * NT + n)) * 64 + d;
                    *(uint32_t*)&df[base] = pack_h2(oe, of);
                } else {
                    float2 bv = *(const float2*)&bias[o];
                    *(float2*)&Cout[(size_t)m * CC + o] = make_float2(e + bv.x, oo + bv.y);
                }
            }
        }
    }
}

// ---------------------------------------------------------------------------
// fp16 tensor-core flash attention, cp.async double-buffered K/V (validated R9).
// grid (13 q-tiles, 64 bh). BQ=128, BK=64, 8 warps x m16 rows.
// ---------------------------------------------------------------------------
#define AST 72
#define QF_B 0
#define KV0_B (128 * AST * 2)            // 18432
#define KVSTG_B (2 * 64 * AST * 2)       // 18432
#define V_B (64 * AST * 2)               // 9216
#define ATTN_SMEM (KV0_B + 2 * KVSTG_B)  // 55296 bytes

__global__ __launch_bounds__(256) void attn_k() {
    extern __shared__ __align__(16) __half smh[];
    const uint32_t sb = smem_u32(smh);

    const int tid = threadIdx.x;
    const int lane = tid & 31;
    const int wid = tid >> 5;
    const int g = lane >> 2;
    const int t = lane & 3;
    const int bh = blockIdx.y;
    const int bb = bh >> 4;
    const int hh = bh & 15;
    const int q0 = blockIdx.x * 128;

    const size_t hb = (size_t)(bb * NH + hh) * NT * 64;

    // Load Q tile
#pragma unroll
    for (int i = 0; i < 4; i++) {
        int idx = i * 256 + tid;
        int r = idx >> 3, c = idx & 7;
        int gr = q0 + r;
        float4 v = make_float4(0.f, 0.f, 0.f, 0.f);
        if (gr < NT) v = ((const float4*)(g_qf + hb + (size_t)gr * 64))[c];
        *(float4*)((char*)smh + QF_B + (r * AST + c * 8) * 2) = v;
    }

    auto issue_kv = [&](int kt, int buf) {
        const int k0 = kt * 64;
        const uint32_t bbs = sb + KV0_B + buf * KVSTG_B;
#pragma unroll
        for (int i = 0; i < 2; i++) {
            int idx = i * 256 + tid;
            int r = idx >> 3, c = idx & 7;
            int gr = k0 + r;
            int sz = (gr < NT) ? 16 : 0;
            int grc = (gr < NT) ? gr : (NT - 1);
            size_t go = hb + (size_t)grc * 64 + c * 8;
            uint32_t so = bbs + (uint32_t)((r * AST + c * 8) * 2);
            cp16z(so,       g_kf + go, sz);
            cp16z(so + V_B, g_vf + go, sz);
        }
    };

    float oacc[8][4];
#pragma unroll
    for (int nd = 0; nd < 8; nd++)
#pragma unroll
        for (int j = 0; j < 4; j++) oacc[nd][j] = 0.f;
    float m2[2] = {-1e30f, -1e30f};
    float l2[2] = {0.f, 0.f};

    const uint32_t a_base = sb + QF_B + 2 * (uint32_t)((wid * 16 + (lane & 15)) * AST + ((lane >> 4) << 3));
    const uint32_t b_roff = (uint32_t)((lane & 7) + ((lane >> 4) << 3));
    const uint32_t b_coff = (uint32_t)(((lane >> 3) & 1) << 3);
    const uint32_t v_roff = (uint32_t)(lane & 15);
    const uint32_t v_coff = (uint32_t)((lane >> 4) << 3);

    issue_kv(0, 0);
    CP_COMMIT();

#pragma unroll 1
    for (int kt = 0; kt < 25; kt++) {
        const int k0 = kt * 64;
        if (kt + 1 < 25) {
            issue_kv(kt + 1, (kt + 1) & 1);
            CP_COMMIT();
            CP_WAIT(1);
        } else {
            CP_WAIT(0);
        }
        __syncthreads();
        const uint32_t kvb = sb + KV0_B + (kt & 1) * KVSTG_B;

        // S = Q K^T
        float sacc[8][4];
#pragma unroll
        for (int ni = 0; ni < 8; ni++)
#pragma unroll
            for (int j = 0; j < 4; j++) sacc[ni][j] = 0.f;

#pragma unroll
        for (int ds = 0; ds < 4; ds++) {
            uint32_t q4[4];
            ldm4(q4, a_base + 2 * (uint32_t)(ds * 16));
#pragma unroll
            for (int ng = 0; ng < 4; ng++) {
                uint32_t k4[4];
                uint32_t be = 2 * (uint32_t)((ng * 16 + b_roff) * AST + ds * 16 + b_coff);
                ldm4(k4, kvb + be);
                mma16816h(sacc[2 * ng],     q4, k4);
                mma16816h(sacc[2 * ng + 1], q4, k4 + 2);
            }
        }

        // Online softmax
        if (k0 + 64 > NT) {
#pragma unroll
            for (int ni = 0; ni < 8; ni++) {
                int c0 = k0 + 8 * ni + 2 * t;
                if (c0 >= NT)     { sacc[ni][0] = -1e30f; sacc[ni][2] = -1e30f; }
                if (c0 + 1 >= NT) { sacc[ni][1] = -1e30f; sacc[ni][3] = -1e30f; }
            }
        }
#pragma unroll
        for (int h2 = 0; h2 < 2; h2++) {
            float mx = -1e30f;
#pragma unroll
            for (int ni = 0; ni < 8; ni++)
                mx = fmaxf(mx, fmaxf(sacc[ni][2 * h2], sacc[ni][2 * h2 + 1]));
            mx = fmaxf(mx, __shfl_xor_sync(0xffffffffu, mx, 1));
            mx = fmaxf(mx, __shfl_xor_sync(0xffffffffu, mx, 2));
            float mn = fmaxf(m2[h2], mx);
            float corr = __expf(m2[h2] - mn);
            m2[h2] = mn;
            float rs = 0.f;
#pragma unroll
            for (int ni = 0; ni < 8; ni++) {
                float p0 = __expf(sacc[ni][2 * h2] - mn);
                float p1 = __expf(sacc[ni][2 * h2 + 1] - mn);
                sacc[ni][2 * h2] = p0;
                sacc[ni][2 * h2 + 1] = p1;
                rs += p0 + p1;
            }
            rs += __shfl_xor_sync(0xffffffffu, rs, 1);
            rs += __shfl_xor_sync(0xffffffffu, rs, 2);
            l2[h2] = l2[h2] * corr + rs;
#pragma unroll
            for (int nd = 0; nd < 8; nd++) {
                oacc[nd][2 * h2] *= corr;
                oacc[nd][2 * h2 + 1] *= corr;
            }
        }

        // O += P V
#pragma unroll
        for (int kc = 0; kc < 4; kc++) {
            uint32_t ph[4];
            ph[0] = pack_h2(sacc[2 * kc][0], sacc[2 * kc][1]);
            ph[1] = pack_h2(sacc[2 * kc][2], sacc[2 * kc][3]);
            ph[2] = pack_h2(sacc[2 * kc + 1][0], sacc[2 * kc + 1][1]);
            ph[3] = pack_h2(sacc[2 * kc + 1][2], sacc[2 * kc + 1][3]);
#pragma unroll
            for (int dg = 0; dg < 4; dg++) {
                uint32_t v4[4];
                uint32_t ve = 2 * (uint32_t)((kc * 16 + v_roff) * AST + dg * 16 + v_coff);
                ldm4t(v4, kvb + V_B + ve);
                mma16816h(oacc[2 * dg],     ph, v4);
                mma16816h(oacc[2 * dg + 1], ph, v4 + 2);
            }
        }
        __syncthreads();
    }

    // Normalize, store fp16 to [B*N][C]
#pragma unroll
    for (int h2 = 0; h2 < 2; h2++) {
        int r = q0 + wid * 16 + g + 8 * h2;
        if (r < NT) {
            float inv = 1.0f / l2[h2];
            size_t ob = (size_t)(bb * NT + r) * CC + hh * 64;
#pragma unroll
            for (int nd = 0; nd < 8; nd++) {
                int col = 8 * nd + 2 * t;
                *(uint32_t*)&g_of[ob + col] =
                    pack_h2(oacc[nd][2 * h2] * inv, oacc[nd][2 * h2 + 1] * inv);
            }
        }
    }
}

// ---------------------------------------------------------------------------
extern "C" void kernel_launch(void* const* d_in, const int* in_sizes, int n_in,
                              void* d_out, int out_size) {
    (void)in_sizes; (void)n_in; (void)out_size;
    const float* x = (const float*)d_in[0];
    const float* wqkv = (const float*)d_in[1];
    const float* wproj = (const float*)d_in[2];
    const float* bproj = (const float*)d_in[3];
    float* out = (float*)d_out;

    cudaFuncSetAttribute(attn_k, cudaFuncAttributeMaxDynamicSharedMemorySize, ATTN_SMEM);
    cudaFuncSetAttribute(gemm_mma<0>, cudaFuncAttributeMaxDynamicSharedMemorySize, GEMM_SMEM);
    cudaFuncSetAttribute(gemm_mma<1>, cudaFuncAttributeMaxDynamicSharedMemorySize, GEMM_SMEM);

    rope_tab_k<<<(NT * 60 + 255) / 256, 256>>>();

    int n4x = MROWS * CC / 4;
    int n4w = 3 * CC * CC / 4;
    int n4p = CC * CC / 4;
    conv_k<<<(n4x + 255) / 256, 256>>>(x, 0, n4x);
    conv_k<<<(n4w + 255) / 256, 256>>>(wqkv, 1, n4w);
    conv_k<<<(n4p + 255) / 256, 256>>>(wproj, 2, n4p);

    gemm_mma<0><<<dim3(24, 49), 256, GEMM_SMEM>>>(nullptr, nullptr);
    attn_k<<<dim3(13, 64), 256, ATTN_SMEM>>>();
    gemm_mma<1><<<dim3(8, 49), 256, GEMM_SMEM>>>(out, bproj);
}

// round 13
// speedup vs baseline: 5.9689x; 1.0805x over previous
#include <cuda_runtime.h>
#include <cuda_bf16.h>
#include <cuda_fp16.h>
#include <cstdint>

// Problem constants
#define BB 4
#define NT 1568
#define NH 16
#define HD 64
#define CC 1024
#define MROWS (BB * NT)          // 6272

// ---------------------------------------------------------------------------
// Scratch (device globals — no allocations allowed)
// ---------------------------------------------------------------------------
static __device__ __align__(16) float g_ctab[NT * 60];
static __device__ __align__(16) float g_stab[NT * 60];
static __device__ __align__(16) __half g_xf[MROWS * CC];
static __device__ __align__(16) __half g_wqf[3 * CC * CC];
static __device__ __align__(16) __half g_wpf[CC * CC];
#define QKVN (BB * NH * NT * HD)
static __device__ __align__(16) __half g_qf[QKVN], g_kf[QKVN], g_vf[QKVN];
static __device__ __align__(16) __half g_of[MROWS * CC];

#define LOG2E 1.44269504088896340736f

// ---------------------------------------------------------------------------
// Baseline-PTX helpers (plain sm_100 target)
// ---------------------------------------------------------------------------
__device__ __forceinline__ uint32_t smem_u32(const void* p) {
    uint32_t a;
    asm("{ .reg .u64 t; cvta.to.shared.u64 t, %1; cvt.u32.u64 %0, t; }" : "=r"(a) : "l"(p));
    return a;
}
__device__ __forceinline__ void ldm4(uint32_t* r, uint32_t addr) {
    asm volatile("ldmatrix.sync.aligned.m8n8.x4.shared.b16 {%0,%1,%2,%3}, [%4];"
                 : "=r"(r[0]), "=r"(r[1]), "=r"(r[2]), "=r"(r[3]) : "r"(addr));
}
__device__ __forceinline__ void ldm4t(uint32_t* r, uint32_t addr) {
    asm volatile("ldmatrix.sync.aligned.m8n8.x4.trans.shared.b16 {%0,%1,%2,%3}, [%4];"
                 : "=r"(r[0]), "=r"(r[1]), "=r"(r[2]), "=r"(r[3]) : "r"(addr));
}
__device__ __forceinline__ void mma16816h(float* c, const uint32_t* a, const uint32_t* b) {
    asm volatile(
        "mma.sync.aligned.m16n8k16.row.col.f32.f16.f16.f32 "
        "{%0,%1,%2,%3}, {%4,%5,%6,%7}, {%8,%9}, {%0,%1,%2,%3};"
        : "+f"(c[0]), "+f"(c[1]), "+f"(c[2]), "+f"(c[3])
        : "r"(a[0]), "r"(a[1]), "r"(a[2]), "r"(a[3]), "r"(b[0]), "r"(b[1]));
}
__device__ __forceinline__ void cp16(uint32_t s, const void* g) {
    asm volatile("cp.async.cg.shared.global [%0], [%1], 16;" :: "r"(s), "l"(g));
}
__device__ __forceinline__ void cp16z(uint32_t s, const void* g, int sz) {
    asm volatile("cp.async.cg.shared.global [%0], [%1], 16, %2;" :: "r"(s), "l"(g), "r"(sz));
}
#define CP_COMMIT() asm volatile("cp.async.commit_group;" ::: "memory")
#define CP_WAIT(n)  asm volatile("cp.async.wait_group %0;" :: "n"(n) : "memory")

__device__ __forceinline__ uint32_t pack_h2(float a, float b) {
    __half2 v = __floats2half2_rn(a, b);
    return *(uint32_t*)&v;
}
__device__ __forceinline__ float ex2(float x) {
    float y;
    asm("ex2.approx.f32 %0, %1;" : "=f"(y) : "f"(x));
    return y;
}

// ---------------------------------------------------------------------------
// RoPE table (validated R4/R6)
// ---------------------------------------------------------------------------
__global__ void rope_tab_k() {
    int i = blockIdx.x * 256 + threadIdx.x;
    if (i >= NT * 60) return;
    int n = i / 60;
    int d = i - n * 60;
    int axis = d / 20;
    int fi = (d % 20) % 10;
    int fr = n / 196;
    int inf = n - fr * 196;
    int hh = inf / 14;
    int ww = inf - hh * 14;
    float pos = (axis == 0) ? (float)fr : ((axis == 1) ? (float)hh : (float)ww);
    float omega = 1.0f / powf(10000.0f, (float)fi * 0.1f);
    g_ctab[i] = cosf(pos * omega);
    g_stab[i] = sinf(pos * omega);
}

// ---------------------------------------------------------------------------
// Fused fp32 -> fp16 conversion of x, Wqkv, Wproj in one launch (grid-stride)
// ---------------------------------------------------------------------------
#define N4X (MROWS * CC / 4)       // 1605632
#define N4W (3 * CC * CC / 4)      //  786432
#define N4P (CC * CC / 4)          //  262144
#define N4ALL (N4X + N4W + N4P)

__global__ void conv_all_k(const float* __restrict__ x,
                           const float* __restrict__ wq,
                           const float* __restrict__ wp) {
    for (int i = blockIdx.x * 256 + threadIdx.x; i < N4ALL; i += gridDim.x * 256) {
        const float* s;
        __half* d;
        int j = i;
        if (j < N4X) { s = x; d = g_xf; }
        else if (j < N4X + N4W) { j -= N4X; s = wq; d = g_wqf; }
        else { j -= N4X + N4W; s = wp; d = g_wpf; }
        float4 v = ((const float4*)s)[j];
        ((uint32_t*)d)[2 * j]     = pack_h2(v.x, v.y);
        ((uint32_t*)d)[2 * j + 1] = pack_h2(v.z, v.w);
    }
}

// ---------------------------------------------------------------------------
// mma.sync fp16 GEMM, cp.async double buffer, ONE sync per stage.
// C = A * B^T (K-major, K=1024). Tile 128x128, BK=32, 8 warps (4m x 2n).
// EPI 0: QKV + RoPE -> fp16 q/k/v (q pre-scaled 0.125*log2e). grid 24x49
// EPI 1: out-projection + bias -> Cout.                       grid  8x49
// ---------------------------------------------------------------------------
#define TILE_B 10240
#define STG_B (2 * TILE_B)
#define OFF_A 0
#define OFF_B (TILE_B)
#define GEMM_SMEM (2 * STG_B)        // 40960 B

template <int EPI>
__global__ __launch_bounds__(256, 2) void gemm_mma(
    float* __restrict__ Cout, const float* __restrict__ bias)
{
    extern __shared__ __align__(16) char sm[];
    const uint32_t sb = smem_u32(sm);

    const int tid = threadIdx.x;
    const int lane = tid & 31;
    const int wid = tid >> 5;
    const int wm = wid & 3;
    const int wn = wid >> 2;
    const int bx = blockIdx.x;
    const int by = blockIdx.y;

    const __half* Ag = (EPI == 0) ? g_xf : g_of;
    const __half* Bg = (EPI == 0) ? g_wqf : g_wpf;

    float acc[2][8][4];
#pragma unroll
    for (int mi = 0; mi < 2; mi++)
#pragma unroll
        for (int ni = 0; ni < 8; ni++)
#pragma unroll
            for (int j = 0; j < 4; j++) acc[mi][ni][j] = 0.0f;

    const int lrow = tid >> 2;
    const int lch = tid & 3;
    const uint32_t a_off = (uint32_t)(((wm * 32 + (lane & 15)) * 40 + ((lane >> 4) << 3)) * 2);
    const uint32_t b_off = (uint32_t)(((wn * 64 + (lane & 7) + ((lane >> 4) << 3)) * 40 +
                                      (((lane >> 3) & 1) << 3)) * 2);

    auto issue_tile = [&](int s, int buf) {
        const int k0 = s * 32;
        const uint32_t bbs = sb + buf * STG_B;
#pragma unroll
        for (int hh = 0; hh < 2; hh++) {
            int r = lrow + hh * 64;
            size_t ga = (size_t)(by * 128 + r) * 1024 + k0 + lch * 8;
            size_t gb = (size_t)(bx * 128 + r) * 1024 + k0 + lch * 8;
            uint32_t so = bbs + (uint32_t)((r * 40 + lch * 8) * 2);
            cp16(so + OFF_A, Ag + ga);
            cp16(so + OFF_B, Bg + gb);
        }
    };

    issue_tile(0, 0);
    CP_COMMIT();

#pragma unroll 1
    for (int s = 0; s < 32; s++) {
        CP_WAIT(0);
        __syncthreads();             // stage-s data visible; all threads done with s-1
        if (s + 1 < 32) {
            issue_tile(s + 1, (s + 1) & 1);   // overlaps compute of stage s
            CP_COMMIT();
        }

        const uint32_t bbs = sb + (s & 1) * STG_B;
#pragma unroll
        for (int ks = 0; ks < 2; ks++) {
            const uint32_t kb = (uint32_t)(ks * 32);
            uint32_t af[2][4];
            ldm4(af[0], bbs + OFF_A + a_off + kb);
            ldm4(af[1], bbs + OFF_A + a_off + kb + 16 * 80);
#pragma unroll
            for (int np = 0; np < 4; np++) {
                uint32_t bf[4];
                ldm4(bf, bbs + OFF_B + b_off + kb + np * 16 * 80);
#pragma unroll
                for (int mi = 0; mi < 2; mi++) {
                    mma16816h(acc[mi][2 * np],     af[mi], bf);
                    mma16816h(acc[mi][2 * np + 1], af[mi], bf + 2);
                }
            }
        }
    }

    const int g = lane >> 2;
    const int t = lane & 3;
#pragma unroll
    for (int mi = 0; mi < 2; mi++) {
#pragma unroll
        for (int ni = 0; ni < 8; ni++) {
#pragma unroll
            for (int half = 0; half < 2; half++) {
                int rr = wm * 32 + mi * 16 + g + half * 8;
                int o = bx * 128 + wn * 64 + ni * 8 + 2 * t;
                float e = acc[mi][ni][2 * half];
                float oo = acc[mi][ni][2 * half + 1];
                int m = by * 128 + rr;
                if (EPI == 0) {
                    int b = m / NT;
                    int n = m - b * NT;
                    int nb = n * 60;
                    int sidx = o >> 10;
                    int hd = (o & 1023) >> 6;
                    int d = o & 63;
                    float oe = e, of = oo;
                    if (sidx < 2 && d < 60) {
                        float c0 = g_ctab[nb + d],     s0 = g_stab[nb + d];
                        float c1 = g_ctab[nb + d + 1], s1 = g_stab[nb + d + 1];
                        oe = fmaf(e, c0, -oo * s0);
                        of = fmaf(oo, c1, e * s1);
                    }
                    if (sidx == 0) { oe *= 0.125f * LOG2E; of *= 0.125f * LOG2E; }
                    __half* df = (sidx == 0) ? g_qf : ((sidx == 1) ? g_kf : g_vf);
                    size_t base = ((size_t)((b * NH + hd) * NT + n)) * 64 + d;
                    *(uint32_t*)&df[base] = pack_h2(oe, of);
                } else {
                    float2 bv = *(const float2*)&bias[o];
                    *(float2*)&Cout[(size_t)m * CC + o] = make_float2(e + bv.x, oo + bv.y);
                }
            }
        }
    }
}

// ---------------------------------------------------------------------------
// fp16 tensor-core flash attention; Q fragments register-resident; one sync
// per KV stage; softmax in log2 domain (q pre-scaled by 0.125*log2e).
// grid (13 q-tiles, 64 bh). BQ=128, BK=64, 8 warps x m16 rows.
// ---------------------------------------------------------------------------
#define AST 72
#define QF_B 0
#define KV0_B (128 * AST * 2)            // 18432
#define KVSTG_B (2 * 64 * AST * 2)       // 18432
#define V_B (64 * AST * 2)               // 9216
#define ATTN_SMEM (KV0_B + 2 * KVSTG_B)  // 55296 bytes

__global__ __launch_bounds__(256, 2) void attn_k() {
    extern __shared__ __align__(16) __half smh[];
    const uint32_t sb = smem_u32(smh);

    const int tid = threadIdx.x;
    const int lane = tid & 31;
    const int wid = tid >> 5;
    const int g = lane >> 2;
    const int t = lane & 3;
    const int bh = blockIdx.y;
    const int bb = bh >> 4;
    const int hh = bh & 15;
    const int q0 = blockIdx.x * 128;

    const size_t hb = (size_t)(bb * NH + hh) * NT * 64;

    // Load Q tile into smem
#pragma unroll
    for (int i = 0; i < 4; i++) {
        int idx = i * 256 + tid;
        int r = idx >> 3, c = idx & 7;
        int gr = q0 + r;
        float4 v = make_float4(0.f, 0.f, 0.f, 0.f);
        if (gr < NT) v = ((const float4*)(g_qf + hb + (size_t)gr * 64))[c];
        *(float4*)((char*)smh + QF_B + (r * AST + c * 8) * 2) = v;
    }

    auto issue_kv = [&](int kt, int buf) {
        const int k0 = kt * 64;
        const uint32_t bbs = sb + KV0_B + buf * KVSTG_B;
#pragma unroll
        for (int i = 0; i < 2; i++) {
            int idx = i * 256 + tid;
            int r = idx >> 3, c = idx & 7;
            int gr = k0 + r;
            int sz = (gr < NT) ? 16 : 0;
            int grc = (gr < NT) ? gr : (NT - 1);
            size_t go = hb + (size_t)grc * 64 + c * 8;
            uint32_t so = bbs + (uint32_t)((r * AST + c * 8) * 2);
            cp16z(so,       g_kf + go, sz);
            cp16z(so + V_B, g_vf + go, sz);
        }
    };

    issue_kv(0, 0);
    CP_COMMIT();
    __syncthreads();   // Q tile stores visible

    // Hoist Q fragments to registers (loop-invariant)
    const uint32_t a_base = sb + QF_B + 2 * (uint32_t)((wid * 16 + (lane & 15)) * AST + ((lane >> 4) << 3));
    uint32_t qfr[4][4];
#pragma unroll
    for (int ds = 0; ds < 4; ds++) ldm4(qfr[ds], a_base + 2 * (uint32_t)(ds * 16));

    const uint32_t b_roff = (uint32_t)((lane & 7) + ((lane >> 4) << 3));
    const uint32_t b_coff = (uint32_t)(((lane >> 3) & 1) << 3);
    const uint32_t v_roff = (uint32_t)(lane & 15);
    const uint32_t v_coff = (uint32_t)((lane >> 4) << 3);

    float oacc[8][4];
#pragma unroll
    for (int nd = 0; nd < 8; nd++)
#pragma unroll
        for (int j = 0; j < 4; j++) oacc[nd][j] = 0.f;
    float m2[2] = {-1e30f, -1e30f};
    float l2[2] = {0.f, 0.f};

#pragma unroll 1
    for (int kt = 0; kt < 25; kt++) {
        const int k0 = kt * 64;
        CP_WAIT(0);
        __syncthreads();             // KV stage visible; all threads done with kt-1
        if (kt + 1 < 25) {
            issue_kv(kt + 1, (kt + 1) & 1);   // overlaps compute of stage kt
            CP_COMMIT();
        }
        const uint32_t kvb = sb + KV0_B + (kt & 1) * KVSTG_B;

        // S = Q K^T (log2-scaled logits; q carries 0.125*log2e)
        float sacc[8][4];
#pragma unroll
        for (int ni = 0; ni < 8; ni++)
#pragma unroll
            for (int j = 0; j < 4; j++) sacc[ni][j] = 0.f;

#pragma unroll
        for (int ds = 0; ds < 4; ds++) {
#pragma unroll
            for (int ng = 0; ng < 4; ng++) {
                uint32_t k4[4];
                uint32_t be = 2 * (uint32_t)((ng * 16 + b_roff) * AST + ds * 16 + b_coff);
                ldm4(k4, kvb + be);
                mma16816h(sacc[2 * ng],     qfr[ds], k4);
                mma16816h(sacc[2 * ng + 1], qfr[ds], k4 + 2);
            }
        }

        // Online softmax (base 2)
        if (k0 + 64 > NT) {
#pragma unroll
            for (int ni = 0; ni < 8; ni++) {
                int c0 = k0 + 8 * ni + 2 * t;
                if (c0 >= NT)     { sacc[ni][0] = -1e30f; sacc[ni][2] = -1e30f; }
                if (c0 + 1 >= NT) { sacc[ni][1] = -1e30f; sacc[ni][3] = -1e30f; }
            }
        }
#pragma unroll
        for (int h2 = 0; h2 < 2; h2++) {
            float mx = -1e30f;
#pragma unroll
            for (int ni = 0; ni < 8; ni++)
                mx = fmaxf(mx, fmaxf(sacc[ni][2 * h2], sacc[ni][2 * h2 + 1]));
            mx = fmaxf(mx, __shfl_xor_sync(0xffffffffu, mx, 1));
            mx = fmaxf(mx, __shfl_xor_sync(0xffffffffu, mx, 2));
            float mn = fmaxf(m2[h2], mx);
            float corr = ex2(m2[h2] - mn);
            m2[h2] = mn;
            float rs = 0.f;
#pragma unroll
            for (int ni = 0; ni < 8; ni++) {
                float p0 = ex2(sacc[ni][2 * h2] - mn);
                float p1 = ex2(sacc[ni][2 * h2 + 1] - mn);
                sacc[ni][2 * h2] = p0;
                sacc[ni][2 * h2 + 1] = p1;
                rs += p0 + p1;
            }
            rs += __shfl_xor_sync(0xffffffffu, rs, 1);
            rs += __shfl_xor_sync(0xffffffffu, rs, 2);
            l2[h2] = l2[h2] * corr + rs;
#pragma unroll
            for (int nd = 0; nd < 8; nd++) {
                oacc[nd][2 * h2] *= corr;
                oacc[nd][2 * h2 + 1] *= corr;
            }
        }

        // O += P V
#pragma unroll
        for (int kc = 0; kc < 4; kc++) {
            uint32_t ph[4];
            ph[0] = pack_h2(sacc[2 * kc][0], sacc[2 * kc][1]);
            ph[1] = pack_h2(sacc[2 * kc][2], sacc[2 * kc][3]);
            ph[2] = pack_h2(sacc[2 * kc + 1][0], sacc[2 * kc + 1][1]);
            ph[3] = pack_h2(sacc[2 * kc + 1][2], sacc[2 * kc + 1][3]);
#pragma unroll
            for (int dg = 0; dg < 4; dg++) {
                uint32_t v4[4];
                uint32_t ve = 2 * (uint32_t)((kc * 16 + v_roff) * AST + dg * 16 + v_coff);
                ldm4t(v4, kvb + V_B + ve);
                mma16816h(oacc[2 * dg],     ph, v4);
                mma16816h(oacc[2 * dg + 1], ph, v4 + 2);
            }
        }
    }

    // Normalize, store fp16 to [B*N][C]
#pragma unroll
    for (int h2 = 0; h2 < 2; h2++) {
        int r = q0 + wid * 16 + g + 8 * h2;
        if (r < NT) {
            float inv = 1.0f / l2[h2];
            size_t ob = (size_t)(bb * NT + r) * CC + hh * 64;
#pragma unroll
            for (int nd = 0; nd < 8; nd++) {
                int col = 8 * nd + 2 * t;
                *(uint32_t*)&g_of[ob + col] =
                    pack_h2(oacc[nd][2 * h2] * inv, oacc[nd][2 * h2 + 1] * inv);
            }
        }
    }
}

// ---------------------------------------------------------------------------
extern "C" void kernel_launch(void* const* d_in, const int* in_sizes, int n_in,
                              void* d_out, int out_size) {
    (void)in_sizes; (void)n_in; (void)out_size;
    const float* x = (const float*)d_in[0];
    const float* wqkv = (const float*)d_in[1];
    const float* wproj = (const float*)d_in[2];
    const float* bproj = (const float*)d_in[3];
    float* out = (float*)d_out;

    cudaFuncSetAttribute(attn_k, cudaFuncAttributeMaxDynamicSharedMemorySize, ATTN_SMEM);
    cudaFuncSetAttribute(gemm_mma<0>, cudaFuncAttributeMaxDynamicSharedMemorySize, GEMM_SMEM);
    cudaFuncSetAttribute(gemm_mma<1>, cudaFuncAttributeMaxDynamicSharedMemorySize, GEMM_SMEM);

    rope_tab_k<<<(NT * 60 + 255) / 256, 256>>>();
    conv_all_k<<<2960, 256>>>(x, wqkv, wproj);

    gemm_mma<0><<<dim3(24, 49), 256, GEMM_SMEM>>>(nullptr, nullptr);
    attn_k<<<dim3(13, 64), 256, ATTN_SMEM>>>();
    gemm_mma<1><<<dim3(8, 49), 256, GEMM_SMEM>>>(out, bproj);
}